// round 12
// baseline (speedup 1.0000x reference)
#include <cuda_runtime.h>
#include <cuda_bf16.h>
#include <cstdint>

// ---------------- problem constants ----------------
#define HN    256
#define BB    64
#define NN    4096
#define TT    100
#define GBLK  32
#define PAD   72          // bf16 elements per smem row (144 B)

#define V_REST_C   (-70.0f)
#define V_RESET_C  (-75.0f)
#define V_THRESH_C (-55.0f)
#define X_LIMIT_EXACT  2.5f
#define X_LIMIT_TENSOR 2.4f

#define KSM1 8      // mma GEMM1 k-split (Kchunk 512)
#define KSM2 16     // GEMM2 k-split (Kchunk 256)
#define KSE1 16     // exact GEMM1 k-split

// ---------------- static device scratch ----------------
__device__ float d_gA[KSE1 * BB * NN];       // GEMM1 partials (mma uses 8 slabs)
__device__ float d_x0p[KSM2 * BB * HN];
__device__ float d_x0[BB * HN];
__device__ __nv_bfloat16 d_spH[BB * NN];     // spikes split hi
__device__ __nv_bfloat16 d_spL[BB * NN];     // spikes split lo
__device__ float d_sp0[BB * HN];
__device__ float d_sp1[BB * HN];
__device__ float d_x1[BB * HN];
__device__ float d_x2[BB * HN];
__device__ unsigned d_barcount;
__device__ unsigned d_bargen;
__device__ unsigned d_need_slow;

// ---------------- helpers ----------------
__device__ __forceinline__ uint32_t cvt_bf2(float x0, float x1) {
    uint32_t r;
    asm("cvt.rn.bf16x2.f32 %0, %1, %2;" : "=r"(r) : "f"(x1), "f"(x0));
    return r;
}
__device__ __forceinline__ uint32_t cvt_bf2_lo(uint32_t h, float x0, float x1) {
    const float d0 = x0 - __uint_as_float(h << 16);
    const float d1 = x1 - __uint_as_float(h & 0xffff0000u);
    return cvt_bf2(d0, d1);
}
__device__ __forceinline__ void fma2(unsigned long long& acc,
                                     unsigned long long a, unsigned long long b) {
    asm("fma.rn.f32x2 %0, %1, %2, %0;" : "+l"(acc) : "l"(a), "l"(b));
}
__device__ __forceinline__ unsigned long long dup2(float a) {
    unsigned long long r;
    asm("mov.b64 %0, {%1, %1};" : "=l"(r) : "f"(a));
    return r;
}
__device__ __forceinline__ void unpack2(unsigned long long p, float& lo, float& hi) {
    asm("mov.b64 {%0, %1}, %2;" : "=f"(lo), "=f"(hi) : "l"(p));
}
__device__ __forceinline__ void cpasync16(uint32_t dst, const void* src) {
    asm volatile("cp.async.cg.shared.global [%0], [%1], 16;" :: "r"(dst), "l"(src));
}
__device__ __forceinline__ void cpasync_commit() {
    asm volatile("cp.async.commit_group;" ::: "memory");
}
template <int N>
__device__ __forceinline__ void cpasync_wait() {
    asm volatile("cp.async.wait_group %0;" :: "n"(N) : "memory");
}
__device__ __forceinline__ void ldmat4(uint32_t* r, uint32_t addr) {
    asm volatile("ldmatrix.sync.aligned.m8n8.x4.shared.b16 {%0,%1,%2,%3}, [%4];"
                 : "=r"(r[0]), "=r"(r[1]), "=r"(r[2]), "=r"(r[3]) : "r"(addr));
}
__device__ __forceinline__ void ldmat4t(uint32_t* r, uint32_t addr) {
    asm volatile("ldmatrix.sync.aligned.m8n8.x4.trans.shared.b16 {%0,%1,%2,%3}, [%4];"
                 : "=r"(r[0]), "=r"(r[1]), "=r"(r[2]), "=r"(r[3]) : "r"(addr));
}
__device__ __forceinline__ void mma16816(float* c, const uint32_t* a,
                                         uint32_t b0, uint32_t b1) {
    asm volatile(
        "mma.sync.aligned.m16n8k16.row.col.f32.bf16.bf16.f32 "
        "{%0,%1,%2,%3}, {%4,%5,%6,%7}, {%8,%9}, {%0,%1,%2,%3};"
        : "+f"(c[0]), "+f"(c[1]), "+f"(c[2]), "+f"(c[3])
        : "r"(a[0]), "r"(a[1]), "r"(a[2]), "r"(a[3]), "r"(b0), "r"(b1));
}

// ---------------- LIF micro-step ----------------
__device__ __forceinline__ void lif_step(float& v, float& isyn, float& refr,
                                         float ib, float& sp) {
    const bool  in_refr = refr > 0.0f;
    const float isyn_u  = isyn + (ib - isyn * 0.2f);
    const float v_u     = v + (isyn_u - (v - V_REST_C)) * 0.05f;
    const bool  spike   = (!in_refr) && (v_u >= V_THRESH_C);
    v    = in_refr ? v    : (spike ? V_RESET_C : v_u);
    isyn = in_refr ? isyn : isyn_u;
    refr = in_refr ? (refr - 1.0f) : (spike ? 2.0f : refr);
    sp   = spike ? 1.0f : 0.0f;
}

// ---------------- grid barrier ----------------
__device__ __forceinline__ void gbar() {
    __syncthreads();
    if (threadIdx.x == 0) {
        __threadfence();
        unsigned gen = *((volatile unsigned*)&d_bargen);
        if (atomicAdd(&d_barcount, 1u) == GBLK - 1u) {
            d_barcount = 0u;
            __threadfence();
            atomicAdd(&d_bargen, 1u);
        } else {
            while (*((volatile unsigned*)&d_bargen) == gen) { }
        }
        __threadfence();
    }
    __syncthreads();
}

// ---------------- prep: zero traces + reset flag + split spikes ------------
__global__ void __launch_bounds__(256) k_prep(float* __restrict__ traces,
                                              const float* __restrict__ spikes) {
    if (blockIdx.x == 0 && threadIdx.x == 0) d_need_slow = 0u;
    const float4 z = {0.f, 0.f, 0.f, 0.f};
    float4* t4 = (float4*)traces;
    int i = blockIdx.x * 256 + threadIdx.x;
    const int stride = gridDim.x * 256;
    const int n4 = (TT * BB * HN) / 4;
    for (int j = i; j < n4; j += stride) t4[j] = z;
    if (blockIdx.x < 256) {           // split spikes (65536 float4s)
        const int i4 = blockIdx.x * 256 + threadIdx.x;
        float4 v = __ldg((const float4*)spikes + i4);
        uint2 h, l;
        h.x = cvt_bf2(v.x, v.y);  l.x = cvt_bf2_lo(h.x, v.x, v.y);
        h.y = cvt_bf2(v.z, v.w);  l.y = cvt_bf2_lo(h.y, v.z, v.w);
        ((uint2*)d_spH)[i4] = h;
        ((uint2*)d_spL)[i4] = l;
    }
}

// ---------------- GEMM1: g partials = spikes(split) @ adj (2-term) ---------
// BM=64, BN=64, BK=64, Kchunk=512 (T=8), grid (64, 8), 128 thr = 4 warps,
// warp tile m32 x n32 (halves B-fragment smem-read redundancy vs 8-warp m16).
__global__ void __launch_bounds__(128) k_g1(
    const __nv_bfloat16* __restrict__ AH, const __nv_bfloat16* __restrict__ AL,
    const float* __restrict__ Bsrc, float* __restrict__ Cp)
{
    extern __shared__ __align__(16) char sm[];
    const uint32_t smBase = (uint32_t)__cvta_generic_to_shared(sm);
    const int AB  = 64 * PAD * 2;        // 9216 B per array
    const int BUF = 3 * AB;              // AH | AL | BH
    const int tid = threadIdx.x;
    const int warp = tid >> 5, lane = tid & 31;
    const int mw = warp & 1, nw = warp >> 1;   // m32 group, n32 group
    const int n0 = blockIdx.x * 64;
    const int k0 = blockIdx.y * 512;

    float acc[2][4][4];                  // [m16 half][n8 j][frag]
#pragma unroll
    for (int h = 0; h < 2; ++h)
#pragma unroll
        for (int j = 0; j < 4; ++j)
#pragma unroll
            for (int c = 0; c < 4; ++c) acc[h][j][c] = 0.f;

    // loaders: A 4 units/thread/array; B row tid>>1, 32 cols (tid&1)*32
    const int br = tid >> 1, bs = (tid & 1) * 32;

    // ldmatrix lane offsets (formulas identical to verified round-11 kernel)
    const int lm_m = lane >> 3, lm_r = lane & 7;
    const uint32_t aOff0 = (uint32_t)(((mw * 32 + (lm_m & 1) * 8 + lm_r) * PAD
                                       + (lm_m >> 1) * 8) * 2);
    const uint32_t aOff1 = aOff0 + (uint32_t)(16 * PAD * 2);
    const uint32_t bOff  = (uint32_t)((((lm_m & 1) * 8 + lm_r) * PAD
                                       + nw * 32 + (lm_m >> 1) * 8) * 2);

    float bf[32];
    // ---- prologue: A(0) cp.async, B(0) regs ----
    {
#pragma unroll
        for (int q = 0; q < 4; ++q) {
            const int u = tid * 4 + q, row = u >> 3, seg = u & 7;
            const uint32_t d = smBase + (uint32_t)((row * PAD + seg * 8) * 2);
            cpasync16(d,      AH + (size_t)row * NN + k0 + seg * 8);
            cpasync16(d + AB, AL + (size_t)row * NN + k0 + seg * 8);
        }
        cpasync_commit();
        const float* bp = Bsrc + (size_t)(k0 + br) * NN + n0 + bs;
#pragma unroll
        for (int w = 0; w < 8; ++w) *(float4*)&bf[4 * w] = __ldg((const float4*)bp + w);
    }

    for (int t = 0; t < 8; ++t) {
        const int cur = t & 1;
        // convert + store B(t): hi-only, [k][n], coalesced STS.128
        {
            uint32_t h[16];
#pragma unroll
            for (int j = 0; j < 16; ++j) h[j] = cvt_bf2(bf[2 * j], bf[2 * j + 1]);
            char* dst = sm + cur * BUF + 2 * AB + (br * PAD + bs) * 2;
            *(uint4*)dst        = make_uint4(h[0],  h[1],  h[2],  h[3]);
            *(uint4*)(dst + 16) = make_uint4(h[4],  h[5],  h[6],  h[7]);
            *(uint4*)(dst + 32) = make_uint4(h[8],  h[9],  h[10], h[11]);
            *(uint4*)(dst + 48) = make_uint4(h[12], h[13], h[14], h[15]);
        }
        if (t + 1 < 8) {
            const int kt = k0 + (t + 1) * 64;
#pragma unroll
            for (int q = 0; q < 4; ++q) {
                const int u = tid * 4 + q, row = u >> 3, seg = u & 7;
                const uint32_t d = smBase + (uint32_t)((cur ^ 1) * BUF)
                                 + (uint32_t)((row * PAD + seg * 8) * 2);
                cpasync16(d,      AH + (size_t)row * NN + kt + seg * 8);
                cpasync16(d + AB, AL + (size_t)row * NN + kt + seg * 8);
            }
            cpasync_commit();
            const float* bp = Bsrc + (size_t)(kt + br) * NN + n0 + bs;
#pragma unroll
            for (int w = 0; w < 8; ++w)
                *(float4*)&bf[4 * w] = __ldg((const float4*)bp + w);
            cpasync_wait<1>();
        } else {
            cpasync_wait<0>();
        }
        __syncthreads();

        const uint32_t base = smBase + (uint32_t)(cur * BUF);
#pragma unroll
        for (int ks = 0; ks < 4; ++ks) {
            uint32_t a0h[4], a1h[4], a0l[4], a1l[4], b0[4], b1[4];
            ldmat4(a0h, base + aOff0 + ks * 32);
            ldmat4(a1h, base + aOff1 + ks * 32);
            ldmat4(a0l, base + AB + aOff0 + ks * 32);
            ldmat4(a1l, base + AB + aOff1 + ks * 32);
            const uint32_t bb = base + 2 * AB + bOff + (uint32_t)(ks * 16 * PAD * 2);
            ldmat4t(b0, bb);
            ldmat4t(b1, bb + 32);
            // half 0 (rows mw*32..+15)
            mma16816(acc[0][0], a0h, b0[0], b0[1]);
            mma16816(acc[0][1], a0h, b0[2], b0[3]);
            mma16816(acc[0][2], a0h, b1[0], b1[1]);
            mma16816(acc[0][3], a0h, b1[2], b1[3]);
            mma16816(acc[0][0], a0l, b0[0], b0[1]);
            mma16816(acc[0][1], a0l, b0[2], b0[3]);
            mma16816(acc[0][2], a0l, b1[0], b1[1]);
            mma16816(acc[0][3], a0l, b1[2], b1[3]);
            // half 1 (rows mw*32+16..+31)
            mma16816(acc[1][0], a1h, b0[0], b0[1]);
            mma16816(acc[1][1], a1h, b0[2], b0[3]);
            mma16816(acc[1][2], a1h, b1[0], b1[1]);
            mma16816(acc[1][3], a1h, b1[2], b1[3]);
            mma16816(acc[1][0], a1l, b0[0], b0[1]);
            mma16816(acc[1][1], a1l, b0[2], b0[3]);
            mma16816(acc[1][2], a1l, b1[0], b1[1]);
            mma16816(acc[1][3], a1l, b1[2], b1[3]);
        }
        __syncthreads();
    }

    float* C = Cp + (size_t)blockIdx.y * (64ull * NN);
    const int g = lane >> 2, tig = lane & 3;
#pragma unroll
    for (int h = 0; h < 2; ++h) {
        const int rbase = mw * 32 + h * 16 + g;
#pragma unroll
        for (int j = 0; j < 4; ++j) {
            const int col = n0 + nw * 32 + j * 8 + tig * 2;
            float2 o0 = {acc[h][j][0], acc[h][j][1]};
            float2 o1 = {acc[h][j][2], acc[h][j][3]};
            *(float2*)&C[(size_t)rbase * NN + col]       = o0;
            *(float2*)&C[(size_t)(rbase + 8) * NN + col] = o1;
        }
    }
}

// ---------------- GEMM2: x0 partials = (sum 8 g slabs) @ W0 (3-term) --------
// BM=64, BN=64, BK=64, Kchunk=256 (T=4), grid (4, 16).
__global__ void __launch_bounds__(256) k_g2(
    const float* __restrict__ A, const float* __restrict__ Bsrc,
    float* __restrict__ Cp)
{
    __shared__ __align__(16) __nv_bfloat16 sAH[64][PAD];
    __shared__ __align__(16) __nv_bfloat16 sAL[64][PAD];
    __shared__ __align__(16) __nv_bfloat16 sBH[64][PAD];
    __shared__ __align__(16) __nv_bfloat16 sBL[64][PAD];
    const int tid = threadIdx.x;
    const int warp = tid >> 5, lane = tid & 31;
    const int mw = warp & 3, nw = warp >> 2;
    const int n0 = blockIdx.x * 64;
    const int k0 = blockIdx.y * 256;

    float acc[4][4];
#pragma unroll
    for (int j = 0; j < 4; ++j)
#pragma unroll
        for (int c = 0; c < 4; ++c) acc[j][c] = 0.f;

    const int ar = tid >> 2, as_ = (tid & 3) * 16;
    const int br = tid >> 2, bs = (tid & 3) * 16;

    const int lm_m = lane >> 3, lm_r = lane & 7;
    const uint32_t aOff = (uint32_t)(((mw * 16 + (lm_m & 1) * 8 + lm_r) * PAD
                                      + (lm_m >> 1) * 8) * 2);
    const uint32_t bOff = (uint32_t)((((lm_m & 1) * 8 + lm_r) * PAD
                                      + nw * 32 + (lm_m >> 1) * 8) * 2);
    const uint32_t aH_b = (uint32_t)__cvta_generic_to_shared(&sAH[0][0]) + aOff;
    const uint32_t aL_b = (uint32_t)__cvta_generic_to_shared(&sAL[0][0]) + aOff;
    const uint32_t bH_b = (uint32_t)__cvta_generic_to_shared(&sBH[0][0]) + bOff;
    const uint32_t bL_b = (uint32_t)__cvta_generic_to_shared(&sBL[0][0]) + bOff;

    float af[16], bf[16];
    {
        const float* ap = A + (size_t)ar * NN + k0 + as_;
#pragma unroll
        for (int w = 0; w < 4; ++w) *(float4*)&af[4 * w] = __ldg((const float4*)ap + w);
#pragma unroll
        for (int p = 1; p < KSM1; ++p) {
            const float* ap2 = ap + (size_t)p * (BB * NN);
#pragma unroll
            for (int w = 0; w < 4; ++w) {
                float4 t = __ldg((const float4*)ap2 + w);
                af[4 * w + 0] += t.x; af[4 * w + 1] += t.y;
                af[4 * w + 2] += t.z; af[4 * w + 3] += t.w;
            }
        }
        const float* bp = Bsrc + (size_t)(k0 + br) * HN + n0 + bs;
#pragma unroll
        for (int w = 0; w < 4; ++w) *(float4*)&bf[4 * w] = __ldg((const float4*)bp + w);
    }

    for (int t = 0; t < 4; ++t) {
        {
            uint32_t h[8], l[8];
#pragma unroll
            for (int j = 0; j < 8; ++j) {
                h[j] = cvt_bf2(af[2 * j], af[2 * j + 1]);
                l[j] = cvt_bf2_lo(h[j], af[2 * j], af[2 * j + 1]);
            }
            *(uint4*)&sAH[ar][as_]     = make_uint4(h[0], h[1], h[2], h[3]);
            *(uint4*)&sAH[ar][as_ + 8] = make_uint4(h[4], h[5], h[6], h[7]);
            *(uint4*)&sAL[ar][as_]     = make_uint4(l[0], l[1], l[2], l[3]);
            *(uint4*)&sAL[ar][as_ + 8] = make_uint4(l[4], l[5], l[6], l[7]);
#pragma unroll
            for (int j = 0; j < 8; ++j) {
                h[j] = cvt_bf2(bf[2 * j], bf[2 * j + 1]);
                l[j] = cvt_bf2_lo(h[j], bf[2 * j], bf[2 * j + 1]);
            }
            *(uint4*)&sBH[br][bs]     = make_uint4(h[0], h[1], h[2], h[3]);
            *(uint4*)&sBH[br][bs + 8] = make_uint4(h[4], h[5], h[6], h[7]);
            *(uint4*)&sBL[br][bs]     = make_uint4(l[0], l[1], l[2], l[3]);
            *(uint4*)&sBL[br][bs + 8] = make_uint4(l[4], l[5], l[6], l[7]);
        }
        if (t + 1 < 4) {
            const int kt = k0 + (t + 1) * 64;
            const float* ap = A + (size_t)ar * NN + kt + as_;
#pragma unroll
            for (int w = 0; w < 4; ++w)
                *(float4*)&af[4 * w] = __ldg((const float4*)ap + w);
#pragma unroll
            for (int p = 1; p < KSM1; ++p) {
                const float* ap2 = ap + (size_t)p * (BB * NN);
#pragma unroll
                for (int w = 0; w < 4; ++w) {
                    float4 tt = __ldg((const float4*)ap2 + w);
                    af[4 * w + 0] += tt.x; af[4 * w + 1] += tt.y;
                    af[4 * w + 2] += tt.z; af[4 * w + 3] += tt.w;
                }
            }
            const float* bp = Bsrc + (size_t)(kt + br) * HN + n0 + bs;
#pragma unroll
            for (int w = 0; w < 4; ++w)
                *(float4*)&bf[4 * w] = __ldg((const float4*)bp + w);
        }
        __syncthreads();

#pragma unroll
        for (int ks = 0; ks < 4; ++ks) {
            uint32_t a0[4], a1[4], b0[4], b1[4], c0[4], c1[4];
            ldmat4(a0, aH_b + ks * 32);
            ldmat4(a1, aL_b + ks * 32);
            ldmat4t(b0, bH_b + (uint32_t)(ks * 16 * PAD * 2));
            ldmat4t(b1, bH_b + (uint32_t)(ks * 16 * PAD * 2) + 32);
            ldmat4t(c0, bL_b + (uint32_t)(ks * 16 * PAD * 2));
            ldmat4t(c1, bL_b + (uint32_t)(ks * 16 * PAD * 2) + 32);
            mma16816(acc[0], a0, b0[0], b0[1]);
            mma16816(acc[1], a0, b0[2], b0[3]);
            mma16816(acc[2], a0, b1[0], b1[1]);
            mma16816(acc[3], a0, b1[2], b1[3]);
            mma16816(acc[0], a0, c0[0], c0[1]);
            mma16816(acc[1], a0, c0[2], c0[3]);
            mma16816(acc[2], a0, c1[0], c1[1]);
            mma16816(acc[3], a0, c1[2], c1[3]);
            mma16816(acc[0], a1, b0[0], b0[1]);
            mma16816(acc[1], a1, b0[2], b0[3]);
            mma16816(acc[2], a1, b1[0], b1[1]);
            mma16816(acc[3], a1, b1[2], b1[3]);
        }
        __syncthreads();
    }

    float* C = Cp + (size_t)blockIdx.y * (64ull * HN);
    const int g = lane >> 2, tig = lane & 3;
#pragma unroll
    for (int j = 0; j < 4; ++j) {
        const int col = n0 + nw * 32 + j * 8 + tig * 2;
        const int r0 = mw * 16 + g;
        float2 o0 = {acc[j][0], acc[j][1]};
        float2 o1 = {acc[j][2], acc[j][3]};
        *(float2*)&C[(size_t)r0 * HN + col]       = o0;
        *(float2*)&C[(size_t)(r0 + 8) * HN + col] = o1;
    }
}

// ---------------- validate: no-spike bound on approx x0 + biases ----------
__global__ void __launch_bounds__(256) k_validate(const float* __restrict__ b0,
                                                  const float* __restrict__ b1,
                                                  const float* __restrict__ b2)
{
    const int tid = threadIdx.x;
    int bad;
    if (blockIdx.x < 64) {
        const int out = blockIdx.x * 256 + tid;
        float s = 0.f;
#pragma unroll
        for (int p = 0; p < KSM2; ++p) s += d_x0p[(size_t)p * (BB * HN) + out];
        s += __ldg(b0 + (out & 255));
        bad = (s >= X_LIMIT_TENSOR);
    } else {
        bad = (__ldg(b1 + tid) >= X_LIMIT_EXACT) ||
              (__ldg(b2 + tid) >= X_LIMIT_EXACT);
    }
    if (__syncthreads_or(bad) && tid == 0) atomicOr(&d_need_slow, 1u);
}

// ---------------- exact f32x2 pipelined SGEMM (guarded fallback) ----------
__device__ __forceinline__ float4 load_a_sum(const float* __restrict__ A,
                                             size_t off, int nsum, int stride) {
    float4 a = __ldg((const float4*)(A + off));
    for (int p = 1; p < nsum; ++p) {
        float4 t = __ldg((const float4*)(A + (size_t)p * stride + off));
        a.x += t.x; a.y += t.y; a.z += t.z; a.w += t.w;
    }
    return a;
}

__global__ void __launch_bounds__(256) k_sgemm_pipe(
    const float* __restrict__ A, const float* __restrict__ B,
    float* __restrict__ Cp, int lda, int Kchunk, int N, int nsum, int slabstride)
{
    if (*((volatile unsigned*)&d_need_slow) == 0u) return;
    __shared__ __align__(16) float As[2][16][64];
    __shared__ __align__(16) float Bs[2][16][256];
    const int tid = threadIdx.x;
    const int n0  = blockIdx.x * 256;
    const int k0  = blockIdx.y * Kchunk;
    const int mg  = tid >> 5;
    const int ng  = tid & 31;
    const int lm  = tid & 63;
    const int lh  = tid >> 6;
    const int bk  = tid >> 4;
    const int bc  = (tid & 15) * 16;
    const int T   = Kchunk >> 4;

    unsigned long long acc[8][4];
#pragma unroll
    for (int i = 0; i < 8; ++i)
#pragma unroll
        for (int p = 0; p < 4; ++p) acc[i][p] = 0ull;

    float4 areg = load_a_sum(A, (size_t)lm * lda + (k0 + lh * 4), nsum, slabstride);
    {
        uint32_t bdst = (uint32_t)__cvta_generic_to_shared(&Bs[0][bk][bc]);
        const float* bp = B + (size_t)(k0 + bk) * N + (n0 + bc);
#pragma unroll
        for (int w = 0; w < 4; ++w) cpasync16(bdst + 16 * w, bp + 4 * w);
        cpasync_commit();
    }

    for (int t = 0; t < T; ++t) {
        const int cur = t & 1;
        {
            const int kb = lh * 4;
            As[cur][kb + 0][lm] = areg.x;  As[cur][kb + 1][lm] = areg.y;
            As[cur][kb + 2][lm] = areg.z;  As[cur][kb + 3][lm] = areg.w;
        }
        if (t + 1 < T) {
            areg = load_a_sum(A, (size_t)lm * lda + (k0 + (t + 1) * 16 + lh * 4),
                              nsum, slabstride);
            uint32_t bdst = (uint32_t)__cvta_generic_to_shared(&Bs[cur ^ 1][bk][bc]);
            const float* bp = B + (size_t)(k0 + (t + 1) * 16 + bk) * N + (n0 + bc);
#pragma unroll
            for (int w = 0; w < 4; ++w) cpasync16(bdst + 16 * w, bp + 4 * w);
            cpasync_commit();
            cpasync_wait<1>();
        } else {
            cpasync_wait<0>();
        }
        __syncthreads();

#pragma unroll 4
        for (int k = 0; k < 16; ++k) {
            float4 alo = *(const float4*)&As[cur][k][mg * 8];
            float4 ahi = *(const float4*)&As[cur][k][mg * 8 + 4];
            unsigned long long ad[8];
            ad[0] = dup2(alo.x); ad[1] = dup2(alo.y);
            ad[2] = dup2(alo.z); ad[3] = dup2(alo.w);
            ad[4] = dup2(ahi.x); ad[5] = dup2(ahi.y);
            ad[6] = dup2(ahi.z); ad[7] = dup2(ahi.w);
            unsigned long long bp_[4];
#pragma unroll
            for (int p = 0; p < 4; ++p)
                bp_[p] = *(const unsigned long long*)&Bs[cur][k][ng * 2 + 64 * p];
#pragma unroll
            for (int i = 0; i < 8; ++i)
#pragma unroll
                for (int p = 0; p < 4; ++p)
                    fma2(acc[i][p], ad[i], bp_[p]);
        }
        __syncthreads();
    }

    float* C = Cp + (size_t)blockIdx.y * (64ull * (size_t)N);
#pragma unroll
    for (int i = 0; i < 8; ++i) {
        const size_t row = (size_t)(mg * 8 + i) * N;
#pragma unroll
        for (int p = 0; p < 4; ++p) {
            float lo, hi;
            unpack2(acc[i][p], lo, hi);
            float2 o = {lo, hi};
            *(float2*)&C[row + n0 + ng * 2 + 64 * p] = o;
        }
    }
}

// ---------------- exact fallback persistent path (guarded) ----------------
__device__ __forceinline__ int stage_to_smem(const float* __restrict__ src,
                                             float* __restrict__ s_x, int tid) {
    const float4* s4 = (const float4*)src;
    float4* dd = (float4*)s_x;
    int flag = 0;
#pragma unroll
    for (int it = 0; it < 16; ++it) {
        const int i = tid + it * 256;
        float4 v = __ldcg(s4 + i);
        flag |= (v.x != 0.f) | (v.y != 0.f) | (v.z != 0.f) | (v.w != 0.f);
        dd[i] = v;
    }
    return flag;
}

__device__ __forceinline__ void gemm_phase(const float* __restrict__ sp,
                                           const float* __restrict__ W,
                                           const float* __restrict__ bias,
                                           float* __restrict__ xout,
                                           int bid, int tid,
                                           float* s_rows, float* s_psum) {
    int flag = 0;
#pragma unroll
    for (int it = 0; it < 2; ++it) {
        const int i = tid + it * 256;
        const float v = __ldcg(sp + bid * 512 + i);
        flag |= (v != 0.f);
        s_rows[i] = v;
    }
    const int tx = tid & 63;
    const int ty = tid >> 6;
    const int c0 = tx * 4;
    const int kb = ty * 64;
    const int any = __syncthreads_or(flag);

    if (any) {
        float4 a0 = {0.f, 0.f, 0.f, 0.f}, a1 = {0.f, 0.f, 0.f, 0.f};
        const float* s0 = s_rows + kb;
        const float* s1 = s_rows + 256 + kb;
#pragma unroll 8
        for (int k = 0; k < 64; ++k) {
            float4 ww = __ldg((const float4*)(W + (size_t)(kb + k) * 256 + c0));
            const float u0 = s0[k], u1 = s1[k];
            a0.x += u0 * ww.x; a0.y += u0 * ww.y; a0.z += u0 * ww.z; a0.w += u0 * ww.w;
            a1.x += u1 * ww.x; a1.y += u1 * ww.y; a1.z += u1 * ww.z; a1.w += u1 * ww.w;
        }
        *(float4*)&s_psum[(ty * 2 + 0) * 256 + c0] = a0;
        *(float4*)&s_psum[(ty * 2 + 1) * 256 + c0] = a1;
        __syncthreads();
        if (ty == 0) {
#pragma unroll
            for (int r = 0; r < 2; ++r) {
                float4 p0 = *(float4*)&s_psum[(0 + r) * 256 + c0];
                float4 p1 = *(float4*)&s_psum[(2 + r) * 256 + c0];
                float4 p2 = *(float4*)&s_psum[(4 + r) * 256 + c0];
                float4 p3 = *(float4*)&s_psum[(6 + r) * 256 + c0];
                float4 bbv = __ldg((const float4*)(bias + c0));
                float4 o;
                o.x = ((p0.x + p1.x) + (p2.x + p3.x)) + bbv.x;
                o.y = ((p0.y + p1.y) + (p2.y + p3.y)) + bbv.y;
                o.z = ((p0.z + p1.z) + (p2.z + p3.z)) + bbv.z;
                o.w = ((p0.w + p1.w) + (p2.w + p3.w)) + bbv.w;
                *(float4*)(xout + (size_t)(bid * 2 + r) * 256 + c0) = o;
            }
        }
        __syncthreads();
    } else {
        if (ty == 0) {
            float4 bbv = __ldg((const float4*)(bias + c0));
#pragma unroll
            for (int r = 0; r < 2; ++r)
                *(float4*)(xout + (size_t)(bid * 2 + r) * 256 + c0) = bbv;
        }
        __syncthreads();
    }
}

__device__ __forceinline__ void lif_scan_layer(const float* __restrict__ xin,
                                               float* __restrict__ spout,
                                               float& v, float& isyn, float& refr,
                                               int tid, float* s_x) {
    int flag = stage_to_smem(xin, s_x, tid);
    flag |= (v != V_REST_C) | (isyn != 0.f) | (refr != 0.f);
    const int any = __syncthreads_or(flag);
    if (any) {
        float nxt = s_x[tid];
#pragma unroll 4
        for (int b = 0; b < 64; ++b) {
            const float ib = nxt;
            if (b < 63) nxt = s_x[(b + 1) * 256 + tid];
            float sp;
            lif_step(v, isyn, refr, ib, sp);
            spout[b * 256 + tid] = sp;
        }
    } else {
        const float4 z = {0.f, 0.f, 0.f, 0.f};
        float4* o4 = (float4*)spout;
#pragma unroll
        for (int it = 0; it < 16; ++it) o4[tid + it * 256] = z;
    }
    __syncthreads();
}

__global__ void __launch_bounds__(256) k_persist_slow(
    const float* __restrict__ b0,
    const float* __restrict__ W1, const float* __restrict__ b1,
    const float* __restrict__ W2, const float* __restrict__ b2,
    float* __restrict__ traces)
{
    if (atomicOr(&d_need_slow, 0u) == 0u) return;

    extern __shared__ float sh[];
    float* s_x    = sh;
    float* s_rows = sh + 16384;
    float* s_psum = sh + 16896;
    const int tid = threadIdx.x;
    const int bid = blockIdx.x;

    // prologue: finalize exact x0 from the KSM2 exact slabs (fused finalize)
#pragma unroll
    for (int e = 0; e < 2; ++e) {
        const int i = bid * 512 + e * 256 + tid;
        float s = 0.f;
#pragma unroll
        for (int p = 0; p < KSM2; ++p) s += d_x0p[(size_t)p * (BB * HN) + i];
        d_x0[i] = s + __ldg(b0 + (i & 255));
    }
    gbar();

    float v0 = V_REST_C, i0 = 0.f, r0 = 0.f;
    float v1 = V_REST_C, i1 = 0.f, r1 = 0.f;
    float v2 = V_REST_C, i2 = 0.f, r2 = 0.f;
    const float* x0pre = d_x0;

    for (int t = 0; t < TT; ++t) {
        if (bid == 0) {
            float nxt = __ldg(x0pre + tid);
#pragma unroll 4
            for (int b = 0; b < 64; ++b) {
                const float ib = nxt;
                if (b < 63) nxt = __ldg(x0pre + (b + 1) * 256 + tid);
                float sp;
                lif_step(v0, i0, r0, ib, sp);
                d_sp0[b * 256 + tid] = sp;
            }
        }
        gbar();
        gemm_phase(d_sp0, W1, b1, d_x1, bid, tid, s_rows, s_psum);
        gbar();
        if (bid == 0) lif_scan_layer(d_x1, d_sp1, v1, i1, r1, tid, s_x);
        gbar();
        gemm_phase(d_sp1, W2, b2, d_x2, bid, tid, s_rows, s_psum);
        gbar();
        if (bid == 0) lif_scan_layer(d_x2, traces + (size_t)t * (BB * HN),
                                     v2, i2, r2, tid, s_x);
    }
}

// ---------------- logits (guarded fast path) ----------------
__global__ void __launch_bounds__(256) k_logits(const float* __restrict__ traces,
                                                const float* __restrict__ Wp,
                                                const float* __restrict__ bp,
                                                float* __restrict__ out)
{
    __shared__ float hrow[HN];
    const int b = blockIdx.x;
    const int tid = threadIdx.x;
    if (*((volatile unsigned*)&d_need_slow) == 0u) {
        if (tid < 5) out[b * 5 + tid] = __ldg(bp + tid);
        return;
    }
    float s = 0.f;
    for (int t = 0; t < TT; ++t)
        s += traces[(size_t)t * (BB * HN) + b * HN + tid];
    hrow[tid] = __fdiv_rn(s, 100.0f);
    __syncthreads();
    if (tid < 5) {
        float acc = 0.f;
        for (int h = 0; h < HN; ++h)
            acc += hrow[h] * __ldg(Wp + h * 5 + tid);
        out[b * 5 + tid] = acc + __ldg(bp + tid);
    }
}

// ---------------- launch ----------------
extern "C" void kernel_launch(void* const* d_in, const int* in_sizes, int n_in,
                              void* d_out, int out_size) {
    const float* spikes = (const float*)d_in[0];
    const float* adj    = (const float*)d_in[1];
    const float* W0     = (const float*)d_in[2];
    const float* b0     = (const float*)d_in[3];
    const float* W1     = (const float*)d_in[4];
    const float* b1     = (const float*)d_in[5];
    const float* W2     = (const float*)d_in[6];
    const float* b2     = (const float*)d_in[7];
    const float* Wp     = (const float*)d_in[8];
    const float* bp     = (const float*)d_in[9];
    float* out = (float*)d_out;        // [logits(64*5) | traces(100*64*256)]
    float* traces = out + BB * 5;

    const int smem_slow = (16384 + 512 + 2048) * (int)sizeof(float);
    const int smem_g1   = 2 * 3 * 64 * PAD * 2;      // 55296 B
    cudaFuncSetAttribute(k_persist_slow, cudaFuncAttributeMaxDynamicSharedMemorySize,
                         smem_slow);
    cudaFuncSetAttribute(k_g1, cudaFuncAttributeMaxDynamicSharedMemorySize,
                         smem_g1);

    void* p;
    cudaGetSymbolAddress(&p, d_gA);   float* gA  = (float*)p;
    cudaGetSymbolAddress(&p, d_x0p);  float* x0p = (float*)p;
    cudaGetSymbolAddress(&p, d_spH);  __nv_bfloat16* spH = (__nv_bfloat16*)p;
    cudaGetSymbolAddress(&p, d_spL);  __nv_bfloat16* spL = (__nv_bfloat16*)p;

    // prep: zero traces + reset flag + split spikes to bf16 hi/lo
    k_prep<<<400, 256>>>(traces, spikes);
    // tensor GEMM1 (2-term): g partials(8) = spikes(split) @ adj
    k_g1<<<dim3(NN / 64, KSM1), 128, smem_g1>>>(spH, spL, adj, gA);
    // tensor GEMM2 (3-term): x0 partials(16) = (sum 8 slabs) @ W0
    k_g2<<<dim3(HN / 64, KSM2), 256>>>(gA, W0, x0p);
    // no-spike validation (approx x0 bound + bias bounds)
    k_validate<<<65, 256>>>(b0, b1, b2);
    // guarded exact recompute (early-exit unless validation tripped)
    k_sgemm_pipe<<<dim3(NN / 256, KSE1), 256>>>(spikes, adj, gA,
                                                NN, NN / KSE1, NN, 1, 0);
    k_sgemm_pipe<<<dim3(HN / 256, KSM2), 256>>>(gA, W0, x0p,
                                                NN, NN / KSM2, HN, KSE1, BB * NN);
    // exact persistent simulation (finalizes x0 in prologue; early-exits
    // when certified spike-free)
    k_persist_slow<<<GBLK, 256, smem_slow>>>(b0, W1, b1, W2, b2, traces);
    // policy head (fast path writes bp directly)
    k_logits<<<BB, 256>>>(traces, Wp, bp, out);
}

// round 13
// speedup vs baseline: 1.3294x; 1.3294x over previous
#include <cuda_runtime.h>
#include <cuda_bf16.h>
#include <cstdint>

// ---------------- problem constants ----------------
#define HN    256
#define BB    64
#define NN    4096
#define TT    100
#define GBLK  32
#define PAD   72          // bf16 elements per smem row (144 B)

#define V_REST_C   (-70.0f)
#define V_RESET_C  (-75.0f)
#define V_THRESH_C (-55.0f)
#define X_LIMIT_EXACT  2.5f
#define X_LIMIT_TENSOR 2.4f

#define KSM1 8      // mma GEMM1 k-split (Kchunk 512)
#define KSM2 32     // GEMM2 k-split (Kchunk 128)
#define KSE1 16     // exact GEMM1 k-split

// ---------------- static device scratch ----------------
__device__ float d_gA[KSE1 * BB * NN];       // GEMM1 partials (mma uses 8 slabs)
__device__ float d_x0p[KSM2 * BB * HN];
__device__ float d_x0[BB * HN];
__device__ __nv_bfloat16 d_spH[BB * NN];     // spikes split hi
__device__ __nv_bfloat16 d_spL[BB * NN];     // spikes split lo
__device__ float d_sp0[BB * HN];
__device__ float d_sp1[BB * HN];
__device__ float d_x1[BB * HN];
__device__ float d_x2[BB * HN];
__device__ unsigned d_barcount;
__device__ unsigned d_bargen;
__device__ unsigned d_need_slow;

// ---------------- helpers ----------------
__device__ __forceinline__ uint32_t cvt_bf2(float x0, float x1) {
    uint32_t r;
    asm("cvt.rn.bf16x2.f32 %0, %1, %2;" : "=r"(r) : "f"(x1), "f"(x0));
    return r;
}
__device__ __forceinline__ uint32_t cvt_bf2_lo(uint32_t h, float x0, float x1) {
    const float d0 = x0 - __uint_as_float(h << 16);
    const float d1 = x1 - __uint_as_float(h & 0xffff0000u);
    return cvt_bf2(d0, d1);
}
__device__ __forceinline__ void fma2(unsigned long long& acc,
                                     unsigned long long a, unsigned long long b) {
    asm("fma.rn.f32x2 %0, %1, %2, %0;" : "+l"(acc) : "l"(a), "l"(b));
}
__device__ __forceinline__ unsigned long long dup2(float a) {
    unsigned long long r;
    asm("mov.b64 %0, {%1, %1};" : "=l"(r) : "f"(a));
    return r;
}
__device__ __forceinline__ void unpack2(unsigned long long p, float& lo, float& hi) {
    asm("mov.b64 {%0, %1}, %2;" : "=f"(lo), "=f"(hi) : "l"(p));
}
__device__ __forceinline__ void cpasync16(uint32_t dst, const void* src) {
    asm volatile("cp.async.cg.shared.global [%0], [%1], 16;" :: "r"(dst), "l"(src));
}
__device__ __forceinline__ void cpasync_commit() {
    asm volatile("cp.async.commit_group;" ::: "memory");
}
template <int N>
__device__ __forceinline__ void cpasync_wait() {
    asm volatile("cp.async.wait_group %0;" :: "n"(N) : "memory");
}
__device__ __forceinline__ void ldmat4(uint32_t* r, uint32_t addr) {
    asm volatile("ldmatrix.sync.aligned.m8n8.x4.shared.b16 {%0,%1,%2,%3}, [%4];"
                 : "=r"(r[0]), "=r"(r[1]), "=r"(r[2]), "=r"(r[3]) : "r"(addr));
}
__device__ __forceinline__ void ldmat4t(uint32_t* r, uint32_t addr) {
    asm volatile("ldmatrix.sync.aligned.m8n8.x4.trans.shared.b16 {%0,%1,%2,%3}, [%4];"
                 : "=r"(r[0]), "=r"(r[1]), "=r"(r[2]), "=r"(r[3]) : "r"(addr));
}
__device__ __forceinline__ void mma16816(float* c, const uint32_t* a,
                                         uint32_t b0, uint32_t b1) {
    asm volatile(
        "mma.sync.aligned.m16n8k16.row.col.f32.bf16.bf16.f32 "
        "{%0,%1,%2,%3}, {%4,%5,%6,%7}, {%8,%9}, {%0,%1,%2,%3};"
        : "+f"(c[0]), "+f"(c[1]), "+f"(c[2]), "+f"(c[3])
        : "r"(a[0]), "r"(a[1]), "r"(a[2]), "r"(a[3]), "r"(b0), "r"(b1));
}

// ---------------- LIF micro-step ----------------
__device__ __forceinline__ void lif_step(float& v, float& isyn, float& refr,
                                         float ib, float& sp) {
    const bool  in_refr = refr > 0.0f;
    const float isyn_u  = isyn + (ib - isyn * 0.2f);
    const float v_u     = v + (isyn_u - (v - V_REST_C)) * 0.05f;
    const bool  spike   = (!in_refr) && (v_u >= V_THRESH_C);
    v    = in_refr ? v    : (spike ? V_RESET_C : v_u);
    isyn = in_refr ? isyn : isyn_u;
    refr = in_refr ? (refr - 1.0f) : (spike ? 2.0f : refr);
    sp   = spike ? 1.0f : 0.0f;
}

// ---------------- grid barrier ----------------
__device__ __forceinline__ void gbar() {
    __syncthreads();
    if (threadIdx.x == 0) {
        __threadfence();
        unsigned gen = *((volatile unsigned*)&d_bargen);
        if (atomicAdd(&d_barcount, 1u) == GBLK - 1u) {
            d_barcount = 0u;
            __threadfence();
            atomicAdd(&d_bargen, 1u);
        } else {
            while (*((volatile unsigned*)&d_bargen) == gen) { }
        }
        __threadfence();
    }
    __syncthreads();
}

// ---------------- prep: zero traces + reset flag + split spikes ------------
__global__ void __launch_bounds__(256) k_prep(float* __restrict__ traces,
                                              const float* __restrict__ spikes) {
    if (blockIdx.x == 0 && threadIdx.x == 0) d_need_slow = 0u;
    const float4 z = {0.f, 0.f, 0.f, 0.f};
    float4* t4 = (float4*)traces;
    int i = blockIdx.x * 256 + threadIdx.x;
    const int stride = gridDim.x * 256;
    const int n4 = (TT * BB * HN) / 4;
    for (int j = i; j < n4; j += stride) t4[j] = z;
    if (blockIdx.x < 256) {           // split spikes (65536 float4s)
        const int i4 = blockIdx.x * 256 + threadIdx.x;
        float4 v = __ldg((const float4*)spikes + i4);
        uint2 h, l;
        h.x = cvt_bf2(v.x, v.y);  l.x = cvt_bf2_lo(h.x, v.x, v.y);
        h.y = cvt_bf2(v.z, v.w);  l.y = cvt_bf2_lo(h.y, v.z, v.w);
        ((uint2*)d_spH)[i4] = h;
        ((uint2*)d_spL)[i4] = l;
    }
}

// ---------------- GEMM1: g partials = spikes(split) @ adj (2-term) ---------
// BM=64, BN=64, BK=64, Kchunk=512 (T=8), grid (64, 8), 256 thr = 8 warps.
// (verified 56.0us configuration)
__global__ void __launch_bounds__(256) k_g1(
    const __nv_bfloat16* __restrict__ AH, const __nv_bfloat16* __restrict__ AL,
    const float* __restrict__ Bsrc, float* __restrict__ Cp)
{
    extern __shared__ __align__(16) char sm[];
    const uint32_t smBase = (uint32_t)__cvta_generic_to_shared(sm);
    const int AB  = 64 * PAD * 2;        // 9216 B per array
    const int BUF = 3 * AB;              // AH | AL | BH
    const int tid = threadIdx.x;
    const int warp = tid >> 5, lane = tid & 31;
    const int mw = warp & 3, nw = warp >> 2;
    const int n0 = blockIdx.x * 64;
    const int k0 = blockIdx.y * 512;

    float acc[4][4];
#pragma unroll
    for (int j = 0; j < 4; ++j)
#pragma unroll
        for (int c = 0; c < 4; ++c) acc[j][c] = 0.f;

    // loaders
    const int u0 = tid * 2;                  // A: 2 16B-units/thread/array
    const int br = tid >> 2, bs = (tid & 3) * 16;   // B: k-row, 16 n

    // ldmatrix lane offsets
    const int lm_m = lane >> 3, lm_r = lane & 7;
    const uint32_t aOff = (uint32_t)(((mw * 16 + (lm_m & 1) * 8 + lm_r) * PAD
                                      + (lm_m >> 1) * 8) * 2);
    const uint32_t bOff = (uint32_t)((((lm_m & 1) * 8 + lm_r) * PAD
                                      + nw * 32 + (lm_m >> 1) * 8) * 2);

    float bf[16];
    // ---- prologue: A(0) cp.async, B(0) regs ----
    {
#pragma unroll
        for (int q = 0; q < 2; ++q) {
            const int u = u0 + q, row = u >> 3, seg = u & 7;
            const uint32_t d = smBase + (uint32_t)((row * PAD + seg * 8) * 2);
            cpasync16(d,      AH + (size_t)row * NN + k0 + seg * 8);
            cpasync16(d + AB, AL + (size_t)row * NN + k0 + seg * 8);
        }
        cpasync_commit();
        const float* bp = Bsrc + (size_t)(k0 + br) * NN + n0 + bs;
#pragma unroll
        for (int w = 0; w < 4; ++w) *(float4*)&bf[4 * w] = __ldg((const float4*)bp + w);
    }

    for (int t = 0; t < 8; ++t) {
        const int cur = t & 1;
        // convert + store B(t): hi-only, [k][n], coalesced STS.128
        {
            uint32_t h[8];
#pragma unroll
            for (int j = 0; j < 8; ++j) h[j] = cvt_bf2(bf[2 * j], bf[2 * j + 1]);
            char* dst = sm + cur * BUF + 2 * AB + (br * PAD + bs) * 2;
            *(uint4*)dst        = make_uint4(h[0], h[1], h[2], h[3]);
            *(uint4*)(dst + 16) = make_uint4(h[4], h[5], h[6], h[7]);
        }
        if (t + 1 < 8) {
            const int kt = k0 + (t + 1) * 64;
#pragma unroll
            for (int q = 0; q < 2; ++q) {
                const int u = u0 + q, row = u >> 3, seg = u & 7;
                const uint32_t d = smBase + (uint32_t)((cur ^ 1) * BUF)
                                 + (uint32_t)((row * PAD + seg * 8) * 2);
                cpasync16(d,      AH + (size_t)row * NN + kt + seg * 8);
                cpasync16(d + AB, AL + (size_t)row * NN + kt + seg * 8);
            }
            cpasync_commit();
            const float* bp = Bsrc + (size_t)(kt + br) * NN + n0 + bs;
#pragma unroll
            for (int w = 0; w < 4; ++w)
                *(float4*)&bf[4 * w] = __ldg((const float4*)bp + w);
            cpasync_wait<1>();
        } else {
            cpasync_wait<0>();
        }
        __syncthreads();

        const uint32_t aH_b = smBase + (uint32_t)(cur * BUF) + aOff;
        const uint32_t bH_b = smBase + (uint32_t)(cur * BUF + 2 * AB) + bOff;
#pragma unroll
        for (int ks = 0; ks < 4; ++ks) {
            uint32_t a0[4], a1[4], b0[4], b1[4];
            ldmat4(a0, aH_b + ks * 32);
            ldmat4(a1, aH_b + AB + ks * 32);
            ldmat4t(b0, bH_b + (uint32_t)(ks * 16 * PAD * 2));
            ldmat4t(b1, bH_b + (uint32_t)(ks * 16 * PAD * 2) + 32);
            mma16816(acc[0], a0, b0[0], b0[1]);
            mma16816(acc[1], a0, b0[2], b0[3]);
            mma16816(acc[2], a0, b1[0], b1[1]);
            mma16816(acc[3], a0, b1[2], b1[3]);
            mma16816(acc[0], a1, b0[0], b0[1]);
            mma16816(acc[1], a1, b0[2], b0[3]);
            mma16816(acc[2], a1, b1[0], b1[1]);
            mma16816(acc[3], a1, b1[2], b1[3]);
        }
        __syncthreads();
    }

    float* C = Cp + (size_t)blockIdx.y * (64ull * NN);
    const int g = lane >> 2, tig = lane & 3;
#pragma unroll
    for (int j = 0; j < 4; ++j) {
        const int col = n0 + nw * 32 + j * 8 + tig * 2;
        const int r0 = mw * 16 + g;
        float2 o0 = {acc[j][0], acc[j][1]};
        float2 o1 = {acc[j][2], acc[j][3]};
        *(float2*)&C[(size_t)r0 * NN + col]       = o0;
        *(float2*)&C[(size_t)(r0 + 8) * NN + col] = o1;
    }
}

// ---------------- GEMM2: x0 partials = (sum 8 g slabs) @ W0 (3-term) --------
// BM=64, BN=64, BK=64, Kchunk=128 (T=2), grid (4, 32).  (verified config)
__global__ void __launch_bounds__(256) k_g2(
    const float* __restrict__ A, const float* __restrict__ Bsrc,
    float* __restrict__ Cp)
{
    __shared__ __align__(16) __nv_bfloat16 sAH[64][PAD];
    __shared__ __align__(16) __nv_bfloat16 sAL[64][PAD];
    __shared__ __align__(16) __nv_bfloat16 sBH[64][PAD];
    __shared__ __align__(16) __nv_bfloat16 sBL[64][PAD];
    const int tid = threadIdx.x;
    const int warp = tid >> 5, lane = tid & 31;
    const int mw = warp & 3, nw = warp >> 2;
    const int n0 = blockIdx.x * 64;
    const int k0 = blockIdx.y * 128;

    float acc[4][4];
#pragma unroll
    for (int j = 0; j < 4; ++j)
#pragma unroll
        for (int c = 0; c < 4; ++c) acc[j][c] = 0.f;

    const int ar = tid >> 2, as_ = (tid & 3) * 16;
    const int br = tid >> 2, bs = (tid & 3) * 16;

    const int lm_m = lane >> 3, lm_r = lane & 7;
    const uint32_t aOff = (uint32_t)(((mw * 16 + (lm_m & 1) * 8 + lm_r) * PAD
                                      + (lm_m >> 1) * 8) * 2);
    const uint32_t bOff = (uint32_t)((((lm_m & 1) * 8 + lm_r) * PAD
                                      + nw * 32 + (lm_m >> 1) * 8) * 2);
    const uint32_t aH_b = (uint32_t)__cvta_generic_to_shared(&sAH[0][0]) + aOff;
    const uint32_t aL_b = (uint32_t)__cvta_generic_to_shared(&sAL[0][0]) + aOff;
    const uint32_t bH_b = (uint32_t)__cvta_generic_to_shared(&sBH[0][0]) + bOff;
    const uint32_t bL_b = (uint32_t)__cvta_generic_to_shared(&sBL[0][0]) + bOff;

    float af[16], bf[16];
    {
        const float* ap = A + (size_t)ar * NN + k0 + as_;
#pragma unroll
        for (int w = 0; w < 4; ++w) *(float4*)&af[4 * w] = __ldg((const float4*)ap + w);
#pragma unroll
        for (int p = 1; p < KSM1; ++p) {
            const float* ap2 = ap + (size_t)p * (BB * NN);
#pragma unroll
            for (int w = 0; w < 4; ++w) {
                float4 t = __ldg((const float4*)ap2 + w);
                af[4 * w + 0] += t.x; af[4 * w + 1] += t.y;
                af[4 * w + 2] += t.z; af[4 * w + 3] += t.w;
            }
        }
        const float* bp = Bsrc + (size_t)(k0 + br) * HN + n0 + bs;
#pragma unroll
        for (int w = 0; w < 4; ++w) *(float4*)&bf[4 * w] = __ldg((const float4*)bp + w);
    }

    for (int t = 0; t < 2; ++t) {
        {
            uint32_t h[8], l[8];
#pragma unroll
            for (int j = 0; j < 8; ++j) {
                h[j] = cvt_bf2(af[2 * j], af[2 * j + 1]);
                l[j] = cvt_bf2_lo(h[j], af[2 * j], af[2 * j + 1]);
            }
            *(uint4*)&sAH[ar][as_]     = make_uint4(h[0], h[1], h[2], h[3]);
            *(uint4*)&sAH[ar][as_ + 8] = make_uint4(h[4], h[5], h[6], h[7]);
            *(uint4*)&sAL[ar][as_]     = make_uint4(l[0], l[1], l[2], l[3]);
            *(uint4*)&sAL[ar][as_ + 8] = make_uint4(l[4], l[5], l[6], l[7]);
#pragma unroll
            for (int j = 0; j < 8; ++j) {
                h[j] = cvt_bf2(bf[2 * j], bf[2 * j + 1]);
                l[j] = cvt_bf2_lo(h[j], bf[2 * j], bf[2 * j + 1]);
            }
            *(uint4*)&sBH[br][bs]     = make_uint4(h[0], h[1], h[2], h[3]);
            *(uint4*)&sBH[br][bs + 8] = make_uint4(h[4], h[5], h[6], h[7]);
            *(uint4*)&sBL[br][bs]     = make_uint4(l[0], l[1], l[2], l[3]);
            *(uint4*)&sBL[br][bs + 8] = make_uint4(l[4], l[5], l[6], l[7]);
        }
        if (t + 1 < 2) {
            const int kt = k0 + 64;
            const float* ap = A + (size_t)ar * NN + kt + as_;
#pragma unroll
            for (int w = 0; w < 4; ++w)
                *(float4*)&af[4 * w] = __ldg((const float4*)ap + w);
#pragma unroll
            for (int p = 1; p < KSM1; ++p) {
                const float* ap2 = ap + (size_t)p * (BB * NN);
#pragma unroll
                for (int w = 0; w < 4; ++w) {
                    float4 tt = __ldg((const float4*)ap2 + w);
                    af[4 * w + 0] += tt.x; af[4 * w + 1] += tt.y;
                    af[4 * w + 2] += tt.z; af[4 * w + 3] += tt.w;
                }
            }
            const float* bp = Bsrc + (size_t)(kt + br) * HN + n0 + bs;
#pragma unroll
            for (int w = 0; w < 4; ++w)
                *(float4*)&bf[4 * w] = __ldg((const float4*)bp + w);
        }
        __syncthreads();

#pragma unroll
        for (int ks = 0; ks < 4; ++ks) {
            uint32_t a0[4], a1[4], b0[4], b1[4], c0[4], c1[4];
            ldmat4(a0, aH_b + ks * 32);
            ldmat4(a1, aL_b + ks * 32);
            ldmat4t(b0, bH_b + (uint32_t)(ks * 16 * PAD * 2));
            ldmat4t(b1, bH_b + (uint32_t)(ks * 16 * PAD * 2) + 32);
            ldmat4t(c0, bL_b + (uint32_t)(ks * 16 * PAD * 2));
            ldmat4t(c1, bL_b + (uint32_t)(ks * 16 * PAD * 2) + 32);
            mma16816(acc[0], a0, b0[0], b0[1]);
            mma16816(acc[1], a0, b0[2], b0[3]);
            mma16816(acc[2], a0, b1[0], b1[1]);
            mma16816(acc[3], a0, b1[2], b1[3]);
            mma16816(acc[0], a0, c0[0], c0[1]);
            mma16816(acc[1], a0, c0[2], c0[3]);
            mma16816(acc[2], a0, c1[0], c1[1]);
            mma16816(acc[3], a0, c1[2], c1[3]);
            mma16816(acc[0], a1, b0[0], b0[1]);
            mma16816(acc[1], a1, b0[2], b0[3]);
            mma16816(acc[2], a1, b1[0], b1[1]);
            mma16816(acc[3], a1, b1[2], b1[3]);
        }
        __syncthreads();
    }

    float* C = Cp + (size_t)blockIdx.y * (64ull * HN);
    const int g = lane >> 2, tig = lane & 3;
#pragma unroll
    for (int j = 0; j < 4; ++j) {
        const int col = n0 + nw * 32 + j * 8 + tig * 2;
        const int r0 = mw * 16 + g;
        float2 o0 = {acc[j][0], acc[j][1]};
        float2 o1 = {acc[j][2], acc[j][3]};
        *(float2*)&C[(size_t)r0 * HN + col]       = o0;
        *(float2*)&C[(size_t)(r0 + 8) * HN + col] = o1;
    }
}

// ---------------- validate (4 threads/output; verified config) -------------
__global__ void __launch_bounds__(256) k_validate(const float* __restrict__ b0,
                                                  const float* __restrict__ b1,
                                                  const float* __restrict__ b2)
{
    __shared__ float red[192];
    const int tid = threadIdx.x;
    int bad = 0;
    if (blockIdx.x < 256) {
        const int o = tid & 63;
        const int out = blockIdx.x * 64 + o;
        const int q = tid >> 6;
        float s = 0.f;
#pragma unroll
        for (int p = 0; p < 8; ++p)
            s += d_x0p[(size_t)(q * 8 + p) * (BB * HN) + out];
        if (q) red[(q - 1) * 64 + o] = s;
        __syncthreads();
        if (!q) {
            const float tot = ((s + red[o]) + (red[64 + o] + red[128 + o]))
                            + __ldg(b0 + (out & 255));
            bad = (tot >= X_LIMIT_TENSOR);
        }
    } else {
        bad = (__ldg(b1 + tid) >= X_LIMIT_EXACT) ||
              (__ldg(b2 + tid) >= X_LIMIT_EXACT);
        __syncthreads();
    }
    if (__syncthreads_or(bad) && tid == 0) atomicOr(&d_need_slow, 1u);
}

// ---------------- exact f32x2 pipelined SGEMM (guarded fallback) ----------
__device__ __forceinline__ float4 load_a_sum(const float* __restrict__ A,
                                             size_t off, int nsum, int stride) {
    float4 a = __ldg((const float4*)(A + off));
    for (int p = 1; p < nsum; ++p) {
        float4 t = __ldg((const float4*)(A + (size_t)p * stride + off));
        a.x += t.x; a.y += t.y; a.z += t.z; a.w += t.w;
    }
    return a;
}

__global__ void __launch_bounds__(256) k_sgemm_pipe(
    const float* __restrict__ A, const float* __restrict__ B,
    float* __restrict__ Cp, int lda, int Kchunk, int N, int nsum, int slabstride)
{
    if (*((volatile unsigned*)&d_need_slow) == 0u) return;
    __shared__ __align__(16) float As[2][16][64];
    __shared__ __align__(16) float Bs[2][16][256];
    const int tid = threadIdx.x;
    const int n0  = blockIdx.x * 256;
    const int k0  = blockIdx.y * Kchunk;
    const int mg  = tid >> 5;
    const int ng  = tid & 31;
    const int lm  = tid & 63;
    const int lh  = tid >> 6;
    const int bk  = tid >> 4;
    const int bc  = (tid & 15) * 16;
    const int T   = Kchunk >> 4;

    unsigned long long acc[8][4];
#pragma unroll
    for (int i = 0; i < 8; ++i)
#pragma unroll
        for (int p = 0; p < 4; ++p) acc[i][p] = 0ull;

    float4 areg = load_a_sum(A, (size_t)lm * lda + (k0 + lh * 4), nsum, slabstride);
    {
        uint32_t bdst = (uint32_t)__cvta_generic_to_shared(&Bs[0][bk][bc]);
        const float* bp = B + (size_t)(k0 + bk) * N + (n0 + bc);
#pragma unroll
        for (int w = 0; w < 4; ++w) cpasync16(bdst + 16 * w, bp + 4 * w);
        cpasync_commit();
    }

    for (int t = 0; t < T; ++t) {
        const int cur = t & 1;
        {
            const int kb = lh * 4;
            As[cur][kb + 0][lm] = areg.x;  As[cur][kb + 1][lm] = areg.y;
            As[cur][kb + 2][lm] = areg.z;  As[cur][kb + 3][lm] = areg.w;
        }
        if (t + 1 < T) {
            areg = load_a_sum(A, (size_t)lm * lda + (k0 + (t + 1) * 16 + lh * 4),
                              nsum, slabstride);
            uint32_t bdst = (uint32_t)__cvta_generic_to_shared(&Bs[cur ^ 1][bk][bc]);
            const float* bp = B + (size_t)(k0 + (t + 1) * 16 + bk) * N + (n0 + bc);
#pragma unroll
            for (int w = 0; w < 4; ++w) cpasync16(bdst + 16 * w, bp + 4 * w);
            cpasync_commit();
            cpasync_wait<1>();
        } else {
            cpasync_wait<0>();
        }
        __syncthreads();

#pragma unroll 4
        for (int k = 0; k < 16; ++k) {
            float4 alo = *(const float4*)&As[cur][k][mg * 8];
            float4 ahi = *(const float4*)&As[cur][k][mg * 8 + 4];
            unsigned long long ad[8];
            ad[0] = dup2(alo.x); ad[1] = dup2(alo.y);
            ad[2] = dup2(alo.z); ad[3] = dup2(alo.w);
            ad[4] = dup2(ahi.x); ad[5] = dup2(ahi.y);
            ad[6] = dup2(ahi.z); ad[7] = dup2(ahi.w);
            unsigned long long bp_[4];
#pragma unroll
            for (int p = 0; p < 4; ++p)
                bp_[p] = *(const unsigned long long*)&Bs[cur][k][ng * 2 + 64 * p];
#pragma unroll
            for (int i = 0; i < 8; ++i)
#pragma unroll
                for (int p = 0; p < 4; ++p)
                    fma2(acc[i][p], ad[i], bp_[p]);
        }
        __syncthreads();
    }

    float* C = Cp + (size_t)blockIdx.y * (64ull * (size_t)N);
#pragma unroll
    for (int i = 0; i < 8; ++i) {
        const size_t row = (size_t)(mg * 8 + i) * N;
#pragma unroll
        for (int p = 0; p < 4; ++p) {
            float lo, hi;
            unpack2(acc[i][p], lo, hi);
            float2 o = {lo, hi};
            *(float2*)&C[row + n0 + ng * 2 + 64 * p] = o;
        }
    }
}

// ---------------- exact fallback persistent path (guarded) ----------------
__device__ __forceinline__ int stage_to_smem(const float* __restrict__ src,
                                             float* __restrict__ s_x, int tid) {
    const float4* s4 = (const float4*)src;
    float4* dd = (float4*)s_x;
    int flag = 0;
#pragma unroll
    for (int it = 0; it < 16; ++it) {
        const int i = tid + it * 256;
        float4 v = __ldcg(s4 + i);
        flag |= (v.x != 0.f) | (v.y != 0.f) | (v.z != 0.f) | (v.w != 0.f);
        dd[i] = v;
    }
    return flag;
}

__device__ __forceinline__ void gemm_phase(const float* __restrict__ sp,
                                           const float* __restrict__ W,
                                           const float* __restrict__ bias,
                                           float* __restrict__ xout,
                                           int bid, int tid,
                                           float* s_rows, float* s_psum) {
    int flag = 0;
#pragma unroll
    for (int it = 0; it < 2; ++it) {
        const int i = tid + it * 256;
        const float v = __ldcg(sp + bid * 512 + i);
        flag |= (v != 0.f);
        s_rows[i] = v;
    }
    const int tx = tid & 63;
    const int ty = tid >> 6;
    const int c0 = tx * 4;
    const int kb = ty * 64;
    const int any = __syncthreads_or(flag);

    if (any) {
        float4 a0 = {0.f, 0.f, 0.f, 0.f}, a1 = {0.f, 0.f, 0.f, 0.f};
        const float* s0 = s_rows + kb;
        const float* s1 = s_rows + 256 + kb;
#pragma unroll 8
        for (int k = 0; k < 64; ++k) {
            float4 ww = __ldg((const float4*)(W + (size_t)(kb + k) * 256 + c0));
            const float u0 = s0[k], u1 = s1[k];
            a0.x += u0 * ww.x; a0.y += u0 * ww.y; a0.z += u0 * ww.z; a0.w += u0 * ww.w;
            a1.x += u1 * ww.x; a1.y += u1 * ww.y; a1.z += u1 * ww.z; a1.w += u1 * ww.w;
        }
        *(float4*)&s_psum[(ty * 2 + 0) * 256 + c0] = a0;
        *(float4*)&s_psum[(ty * 2 + 1) * 256 + c0] = a1;
        __syncthreads();
        if (ty == 0) {
#pragma unroll
            for (int r = 0; r < 2; ++r) {
                float4 p0 = *(float4*)&s_psum[(0 + r) * 256 + c0];
                float4 p1 = *(float4*)&s_psum[(2 + r) * 256 + c0];
                float4 p2 = *(float4*)&s_psum[(4 + r) * 256 + c0];
                float4 p3 = *(float4*)&s_psum[(6 + r) * 256 + c0];
                float4 bbv = __ldg((const float4*)(bias + c0));
                float4 o;
                o.x = ((p0.x + p1.x) + (p2.x + p3.x)) + bbv.x;
                o.y = ((p0.y + p1.y) + (p2.y + p3.y)) + bbv.y;
                o.z = ((p0.z + p1.z) + (p2.z + p3.z)) + bbv.z;
                o.w = ((p0.w + p1.w) + (p2.w + p3.w)) + bbv.w;
                *(float4*)(xout + (size_t)(bid * 2 + r) * 256 + c0) = o;
            }
        }
        __syncthreads();
    } else {
        if (ty == 0) {
            float4 bbv = __ldg((const float4*)(bias + c0));
#pragma unroll
            for (int r = 0; r < 2; ++r)
                *(float4*)(xout + (size_t)(bid * 2 + r) * 256 + c0) = bbv;
        }
        __syncthreads();
    }
}

__device__ __forceinline__ void lif_scan_layer(const float* __restrict__ xin,
                                               float* __restrict__ spout,
                                               float& v, float& isyn, float& refr,
                                               int tid, float* s_x) {
    int flag = stage_to_smem(xin, s_x, tid);
    flag |= (v != V_REST_C) | (isyn != 0.f) | (refr != 0.f);
    const int any = __syncthreads_or(flag);
    if (any) {
        float nxt = s_x[tid];
#pragma unroll 4
        for (int b = 0; b < 64; ++b) {
            const float ib = nxt;
            if (b < 63) nxt = s_x[(b + 1) * 256 + tid];
            float sp;
            lif_step(v, isyn, refr, ib, sp);
            spout[b * 256 + tid] = sp;
        }
    } else {
        const float4 z = {0.f, 0.f, 0.f, 0.f};
        float4* o4 = (float4*)spout;
#pragma unroll
        for (int it = 0; it < 16; ++it) o4[tid + it * 256] = z;
    }
    __syncthreads();
}

__global__ void __launch_bounds__(256) k_persist_slow(
    const float* __restrict__ b0,
    const float* __restrict__ W1, const float* __restrict__ b1,
    const float* __restrict__ W2, const float* __restrict__ b2,
    float* __restrict__ traces)
{
    if (atomicOr(&d_need_slow, 0u) == 0u) return;

    extern __shared__ float sh[];
    float* s_x    = sh;
    float* s_rows = sh + 16384;
    float* s_psum = sh + 16896;
    const int tid = threadIdx.x;
    const int bid = blockIdx.x;

    // prologue: finalize exact x0 from the KSM2 exact slabs (fused finalize)
#pragma unroll
    for (int e = 0; e < 2; ++e) {
        const int i = bid * 512 + e * 256 + tid;
        float s = 0.f;
#pragma unroll 8
        for (int p = 0; p < KSM2; ++p) s += d_x0p[(size_t)p * (BB * HN) + i];
        d_x0[i] = s + __ldg(b0 + (i & 255));
    }
    gbar();

    float v0 = V_REST_C, i0 = 0.f, r0 = 0.f;
    float v1 = V_REST_C, i1 = 0.f, r1 = 0.f;
    float v2 = V_REST_C, i2 = 0.f, r2 = 0.f;
    const float* x0pre = d_x0;

    for (int t = 0; t < TT; ++t) {
        if (bid == 0) {
            float nxt = __ldg(x0pre + tid);
#pragma unroll 4
            for (int b = 0; b < 64; ++b) {
                const float ib = nxt;
                if (b < 63) nxt = __ldg(x0pre + (b + 1) * 256 + tid);
                float sp;
                lif_step(v0, i0, r0, ib, sp);
                d_sp0[b * 256 + tid] = sp;
            }
        }
        gbar();
        gemm_phase(d_sp0, W1, b1, d_x1, bid, tid, s_rows, s_psum);
        gbar();
        if (bid == 0) lif_scan_layer(d_x1, d_sp1, v1, i1, r1, tid, s_x);
        gbar();
        gemm_phase(d_sp1, W2, b2, d_x2, bid, tid, s_rows, s_psum);
        gbar();
        if (bid == 0) lif_scan_layer(d_x2, traces + (size_t)t * (BB * HN),
                                     v2, i2, r2, tid, s_x);
    }
}

// ---------------- logits (guarded fast path) ----------------
__global__ void __launch_bounds__(256) k_logits(const float* __restrict__ traces,
                                                const float* __restrict__ Wp,
                                                const float* __restrict__ bp,
                                                float* __restrict__ out)
{
    __shared__ float hrow[HN];
    const int b = blockIdx.x;
    const int tid = threadIdx.x;
    if (*((volatile unsigned*)&d_need_slow) == 0u) {
        if (tid < 5) out[b * 5 + tid] = __ldg(bp + tid);
        return;
    }
    float s = 0.f;
    for (int t = 0; t < TT; ++t)
        s += traces[(size_t)t * (BB * HN) + b * HN + tid];
    hrow[tid] = __fdiv_rn(s, 100.0f);
    __syncthreads();
    if (tid < 5) {
        float acc = 0.f;
        for (int h = 0; h < HN; ++h)
            acc += hrow[h] * __ldg(Wp + h * 5 + tid);
        out[b * 5 + tid] = acc + __ldg(bp + tid);
    }
}

// ---------------- launch ----------------
extern "C" void kernel_launch(void* const* d_in, const int* in_sizes, int n_in,
                              void* d_out, int out_size) {
    const float* spikes = (const float*)d_in[0];
    const float* adj    = (const float*)d_in[1];
    const float* W0     = (const float*)d_in[2];
    const float* b0     = (const float*)d_in[3];
    const float* W1     = (const float*)d_in[4];
    const float* b1     = (const float*)d_in[5];
    const float* W2     = (const float*)d_in[6];
    const float* b2     = (const float*)d_in[7];
    const float* Wp     = (const float*)d_in[8];
    const float* bp     = (const float*)d_in[9];
    float* out = (float*)d_out;        // [logits(64*5) | traces(100*64*256)]
    float* traces = out + BB * 5;

    const int smem_slow = (16384 + 512 + 2048) * (int)sizeof(float);
    const int smem_g1   = 2 * 3 * 64 * PAD * 2;      // 55296 B
    cudaFuncSetAttribute(k_persist_slow, cudaFuncAttributeMaxDynamicSharedMemorySize,
                         smem_slow);
    cudaFuncSetAttribute(k_g1, cudaFuncAttributeMaxDynamicSharedMemorySize,
                         smem_g1);

    void* p;
    cudaGetSymbolAddress(&p, d_gA);   float* gA  = (float*)p;
    cudaGetSymbolAddress(&p, d_x0p);  float* x0p = (float*)p;
    cudaGetSymbolAddress(&p, d_spH);  __nv_bfloat16* spH = (__nv_bfloat16*)p;
    cudaGetSymbolAddress(&p, d_spL);  __nv_bfloat16* spL = (__nv_bfloat16*)p;

    // prep: zero traces + reset flag + split spikes to bf16 hi/lo
    k_prep<<<400, 256>>>(traces, spikes);
    // tensor GEMM1 (2-term): g partials(8) = spikes(split) @ adj
    k_g1<<<dim3(NN / 64, KSM1), 256, smem_g1>>>(spH, spL, adj, gA);
    // tensor GEMM2 (3-term): x0 partials(32) = (sum 8 slabs) @ W0
    k_g2<<<dim3(HN / 64, KSM2), 256>>>(gA, W0, x0p);
    // no-spike validation (approx x0 bound + bias bounds)
    k_validate<<<257, 256>>>(b0, b1, b2);
    // guarded exact recompute (early-exit unless validation tripped)
    k_sgemm_pipe<<<dim3(NN / 256, KSE1), 256>>>(spikes, adj, gA,
                                                NN, NN / KSE1, NN, 1, 0);
    k_sgemm_pipe<<<dim3(HN / 256, KSM2), 256>>>(gA, W0, x0p,
                                                NN, NN / KSM2, HN, KSE1, BB * NN);
    // exact persistent simulation (finalizes x0 in prologue; early-exits
    // when certified spike-free)
    k_persist_slow<<<GBLK, 256, smem_slow>>>(b0, W1, b1, W2, b2, traces);
    // policy head (fast path writes bp directly)
    k_logits<<<BB, 256>>>(traces, Wp, bp, out);
}

// round 14
// speedup vs baseline: 1.3960x; 1.0501x over previous
#include <cuda_runtime.h>
#include <cuda_bf16.h>
#include <cstdint>

// ---------------- problem constants ----------------
#define HN    256
#define BB    64
#define NN    4096
#define TT    100
#define GBLK  32
#define PAD   72          // bf16 elements per smem row (144 B)

#define V_REST_C   (-70.0f)
#define V_RESET_C  (-75.0f)
#define V_THRESH_C (-55.0f)
#define X_LIMIT_EXACT  2.5f
#define X_LIMIT_TENSOR 2.4f

#define KSM1 8      // mma GEMM1 k-split (Kchunk 512)
#define KSM2 32     // GEMM2 k-split (Kchunk 128)

// ---------------- static device scratch ----------------
__device__ float d_gA[KSM1 * BB * NN];       // GEMM1 mma partials (8 slabs)
__device__ float d_x0p[KSM2 * BB * HN];
__device__ float d_x0[BB * HN];
__device__ __nv_bfloat16 d_spH[BB * NN];     // spikes split hi
__device__ __nv_bfloat16 d_spL[BB * NN];     // spikes split lo
__device__ float d_sp0[BB * HN];
__device__ float d_sp1[BB * HN];
__device__ float d_x1[BB * HN];
__device__ float d_x2[BB * HN];
__device__ unsigned d_barcount;
__device__ unsigned d_bargen;
__device__ unsigned d_need_slow;

// ---------------- helpers ----------------
__device__ __forceinline__ uint32_t cvt_bf2(float x0, float x1) {
    uint32_t r;
    asm("cvt.rn.bf16x2.f32 %0, %1, %2;" : "=r"(r) : "f"(x1), "f"(x0));
    return r;
}
__device__ __forceinline__ uint32_t cvt_bf2_lo(uint32_t h, float x0, float x1) {
    const float d0 = x0 - __uint_as_float(h << 16);
    const float d1 = x1 - __uint_as_float(h & 0xffff0000u);
    return cvt_bf2(d0, d1);
}
__device__ __forceinline__ void cpasync16(uint32_t dst, const void* src) {
    asm volatile("cp.async.cg.shared.global [%0], [%1], 16;" :: "r"(dst), "l"(src));
}
__device__ __forceinline__ void cpasync_commit() {
    asm volatile("cp.async.commit_group;" ::: "memory");
}
template <int N>
__device__ __forceinline__ void cpasync_wait() {
    asm volatile("cp.async.wait_group %0;" :: "n"(N) : "memory");
}
__device__ __forceinline__ void ldmat4(uint32_t* r, uint32_t addr) {
    asm volatile("ldmatrix.sync.aligned.m8n8.x4.shared.b16 {%0,%1,%2,%3}, [%4];"
                 : "=r"(r[0]), "=r"(r[1]), "=r"(r[2]), "=r"(r[3]) : "r"(addr));
}
__device__ __forceinline__ void ldmat4t(uint32_t* r, uint32_t addr) {
    asm volatile("ldmatrix.sync.aligned.m8n8.x4.trans.shared.b16 {%0,%1,%2,%3}, [%4];"
                 : "=r"(r[0]), "=r"(r[1]), "=r"(r[2]), "=r"(r[3]) : "r"(addr));
}
__device__ __forceinline__ void mma16816(float* c, const uint32_t* a,
                                         uint32_t b0, uint32_t b1) {
    asm volatile(
        "mma.sync.aligned.m16n8k16.row.col.f32.bf16.bf16.f32 "
        "{%0,%1,%2,%3}, {%4,%5,%6,%7}, {%8,%9}, {%0,%1,%2,%3};"
        : "+f"(c[0]), "+f"(c[1]), "+f"(c[2]), "+f"(c[3])
        : "r"(a[0]), "r"(a[1]), "r"(a[2]), "r"(a[3]), "r"(b0), "r"(b1));
}

// ---------------- LIF micro-step ----------------
__device__ __forceinline__ void lif_step(float& v, float& isyn, float& refr,
                                         float ib, float& sp) {
    const bool  in_refr = refr > 0.0f;
    const float isyn_u  = isyn + (ib - isyn * 0.2f);
    const float v_u     = v + (isyn_u - (v - V_REST_C)) * 0.05f;
    const bool  spike   = (!in_refr) && (v_u >= V_THRESH_C);
    v    = in_refr ? v    : (spike ? V_RESET_C : v_u);
    isyn = in_refr ? isyn : isyn_u;
    refr = in_refr ? (refr - 1.0f) : (spike ? 2.0f : refr);
    sp   = spike ? 1.0f : 0.0f;
}

// ---------------- grid barrier ----------------
__device__ __forceinline__ void gbar() {
    __syncthreads();
    if (threadIdx.x == 0) {
        __threadfence();
        unsigned gen = *((volatile unsigned*)&d_bargen);
        if (atomicAdd(&d_barcount, 1u) == GBLK - 1u) {
            d_barcount = 0u;
            __threadfence();
            atomicAdd(&d_bargen, 1u);
        } else {
            while (*((volatile unsigned*)&d_bargen) == gen) { }
        }
        __threadfence();
    }
    __syncthreads();
}

// ---------------- prep: zero traces + reset flag + split spikes ------------
__global__ void __launch_bounds__(256) k_prep(float* __restrict__ traces,
                                              const float* __restrict__ spikes) {
    if (blockIdx.x == 0 && threadIdx.x == 0) d_need_slow = 0u;
    const float4 z = {0.f, 0.f, 0.f, 0.f};
    float4* t4 = (float4*)traces;
    int i = blockIdx.x * 256 + threadIdx.x;
    const int stride = gridDim.x * 256;
    const int n4 = (TT * BB * HN) / 4;
    for (int j = i; j < n4; j += stride) t4[j] = z;
    if (blockIdx.x < 256) {           // split spikes (65536 float4s)
        const int i4 = blockIdx.x * 256 + threadIdx.x;
        float4 v = __ldg((const float4*)spikes + i4);
        uint2 h, l;
        h.x = cvt_bf2(v.x, v.y);  l.x = cvt_bf2_lo(h.x, v.x, v.y);
        h.y = cvt_bf2(v.z, v.w);  l.y = cvt_bf2_lo(h.y, v.z, v.w);
        ((uint2*)d_spH)[i4] = h;
        ((uint2*)d_spL)[i4] = l;
    }
}

// ---------------- GEMM1: g partials = spikes(split) @ adj (2-term) ---------
// BM=64, BN=64, BK=64, Kchunk=512 (T=8), grid (64, 8), 256 thr = 8 warps.
// (verified 54.3us configuration — unchanged)
__global__ void __launch_bounds__(256) k_g1(
    const __nv_bfloat16* __restrict__ AH, const __nv_bfloat16* __restrict__ AL,
    const float* __restrict__ Bsrc, float* __restrict__ Cp)
{
    extern __shared__ __align__(16) char sm[];
    const uint32_t smBase = (uint32_t)__cvta_generic_to_shared(sm);
    const int AB  = 64 * PAD * 2;        // 9216 B per array
    const int BUF = 3 * AB;              // AH | AL | BH
    const int tid = threadIdx.x;
    const int warp = tid >> 5, lane = tid & 31;
    const int mw = warp & 3, nw = warp >> 2;
    const int n0 = blockIdx.x * 64;
    const int k0 = blockIdx.y * 512;

    float acc[4][4];
#pragma unroll
    for (int j = 0; j < 4; ++j)
#pragma unroll
        for (int c = 0; c < 4; ++c) acc[j][c] = 0.f;

    const int u0 = tid * 2;
    const int br = tid >> 2, bs = (tid & 3) * 16;

    const int lm_m = lane >> 3, lm_r = lane & 7;
    const uint32_t aOff = (uint32_t)(((mw * 16 + (lm_m & 1) * 8 + lm_r) * PAD
                                      + (lm_m >> 1) * 8) * 2);
    const uint32_t bOff = (uint32_t)((((lm_m & 1) * 8 + lm_r) * PAD
                                      + nw * 32 + (lm_m >> 1) * 8) * 2);

    float bf[16];
    {
#pragma unroll
        for (int q = 0; q < 2; ++q) {
            const int u = u0 + q, row = u >> 3, seg = u & 7;
            const uint32_t d = smBase + (uint32_t)((row * PAD + seg * 8) * 2);
            cpasync16(d,      AH + (size_t)row * NN + k0 + seg * 8);
            cpasync16(d + AB, AL + (size_t)row * NN + k0 + seg * 8);
        }
        cpasync_commit();
        const float* bp = Bsrc + (size_t)(k0 + br) * NN + n0 + bs;
#pragma unroll
        for (int w = 0; w < 4; ++w) *(float4*)&bf[4 * w] = __ldg((const float4*)bp + w);
    }

    for (int t = 0; t < 8; ++t) {
        const int cur = t & 1;
        {
            uint32_t h[8];
#pragma unroll
            for (int j = 0; j < 8; ++j) h[j] = cvt_bf2(bf[2 * j], bf[2 * j + 1]);
            char* dst = sm + cur * BUF + 2 * AB + (br * PAD + bs) * 2;
            *(uint4*)dst        = make_uint4(h[0], h[1], h[2], h[3]);
            *(uint4*)(dst + 16) = make_uint4(h[4], h[5], h[6], h[7]);
        }
        if (t + 1 < 8) {
            const int kt = k0 + (t + 1) * 64;
#pragma unroll
            for (int q = 0; q < 2; ++q) {
                const int u = u0 + q, row = u >> 3, seg = u & 7;
                const uint32_t d = smBase + (uint32_t)((cur ^ 1) * BUF)
                                 + (uint32_t)((row * PAD + seg * 8) * 2);
                cpasync16(d,      AH + (size_t)row * NN + kt + seg * 8);
                cpasync16(d + AB, AL + (size_t)row * NN + kt + seg * 8);
            }
            cpasync_commit();
            const float* bp = Bsrc + (size_t)(kt + br) * NN + n0 + bs;
#pragma unroll
            for (int w = 0; w < 4; ++w)
                *(float4*)&bf[4 * w] = __ldg((const float4*)bp + w);
            cpasync_wait<1>();
        } else {
            cpasync_wait<0>();
        }
        __syncthreads();

        const uint32_t aH_b = smBase + (uint32_t)(cur * BUF) + aOff;
        const uint32_t bH_b = smBase + (uint32_t)(cur * BUF + 2 * AB) + bOff;
#pragma unroll
        for (int ks = 0; ks < 4; ++ks) {
            uint32_t a0[4], a1[4], b0[4], b1[4];
            ldmat4(a0, aH_b + ks * 32);
            ldmat4(a1, aH_b + AB + ks * 32);
            ldmat4t(b0, bH_b + (uint32_t)(ks * 16 * PAD * 2));
            ldmat4t(b1, bH_b + (uint32_t)(ks * 16 * PAD * 2) + 32);
            mma16816(acc[0], a0, b0[0], b0[1]);
            mma16816(acc[1], a0, b0[2], b0[3]);
            mma16816(acc[2], a0, b1[0], b1[1]);
            mma16816(acc[3], a0, b1[2], b1[3]);
            mma16816(acc[0], a1, b0[0], b0[1]);
            mma16816(acc[1], a1, b0[2], b0[3]);
            mma16816(acc[2], a1, b1[0], b1[1]);
            mma16816(acc[3], a1, b1[2], b1[3]);
        }
        __syncthreads();
    }

    float* C = Cp + (size_t)blockIdx.y * (64ull * NN);
    const int g = lane >> 2, tig = lane & 3;
#pragma unroll
    for (int j = 0; j < 4; ++j) {
        const int col = n0 + nw * 32 + j * 8 + tig * 2;
        const int r0 = mw * 16 + g;
        float2 o0 = {acc[j][0], acc[j][1]};
        float2 o1 = {acc[j][2], acc[j][3]};
        *(float2*)&C[(size_t)r0 * NN + col]       = o0;
        *(float2*)&C[(size_t)(r0 + 8) * NN + col] = o1;
    }
}

// ---------------- GEMM2: x0 partials = (sum 8 g slabs) @ W0 (3-term) --------
// BM=64, BN=64, BK=64, Kchunk=128 (T=2), grid (4, 32).  (verified — unchanged)
__global__ void __launch_bounds__(256) k_g2(
    const float* __restrict__ A, const float* __restrict__ Bsrc,
    float* __restrict__ Cp)
{
    __shared__ __align__(16) __nv_bfloat16 sAH[64][PAD];
    __shared__ __align__(16) __nv_bfloat16 sAL[64][PAD];
    __shared__ __align__(16) __nv_bfloat16 sBH[64][PAD];
    __shared__ __align__(16) __nv_bfloat16 sBL[64][PAD];
    const int tid = threadIdx.x;
    const int warp = tid >> 5, lane = tid & 31;
    const int mw = warp & 3, nw = warp >> 2;
    const int n0 = blockIdx.x * 64;
    const int k0 = blockIdx.y * 128;

    float acc[4][4];
#pragma unroll
    for (int j = 0; j < 4; ++j)
#pragma unroll
        for (int c = 0; c < 4; ++c) acc[j][c] = 0.f;

    const int ar = tid >> 2, as_ = (tid & 3) * 16;
    const int br = tid >> 2, bs = (tid & 3) * 16;

    const int lm_m = lane >> 3, lm_r = lane & 7;
    const uint32_t aOff = (uint32_t)(((mw * 16 + (lm_m & 1) * 8 + lm_r) * PAD
                                      + (lm_m >> 1) * 8) * 2);
    const uint32_t bOff = (uint32_t)((((lm_m & 1) * 8 + lm_r) * PAD
                                      + nw * 32 + (lm_m >> 1) * 8) * 2);
    const uint32_t aH_b = (uint32_t)__cvta_generic_to_shared(&sAH[0][0]) + aOff;
    const uint32_t aL_b = (uint32_t)__cvta_generic_to_shared(&sAL[0][0]) + aOff;
    const uint32_t bH_b = (uint32_t)__cvta_generic_to_shared(&sBH[0][0]) + bOff;
    const uint32_t bL_b = (uint32_t)__cvta_generic_to_shared(&sBL[0][0]) + bOff;

    float af[16], bf[16];
    {
        const float* ap = A + (size_t)ar * NN + k0 + as_;
#pragma unroll
        for (int w = 0; w < 4; ++w) *(float4*)&af[4 * w] = __ldg((const float4*)ap + w);
#pragma unroll
        for (int p = 1; p < KSM1; ++p) {
            const float* ap2 = ap + (size_t)p * (BB * NN);
#pragma unroll
            for (int w = 0; w < 4; ++w) {
                float4 t = __ldg((const float4*)ap2 + w);
                af[4 * w + 0] += t.x; af[4 * w + 1] += t.y;
                af[4 * w + 2] += t.z; af[4 * w + 3] += t.w;
            }
        }
        const float* bp = Bsrc + (size_t)(k0 + br) * HN + n0 + bs;
#pragma unroll
        for (int w = 0; w < 4; ++w) *(float4*)&bf[4 * w] = __ldg((const float4*)bp + w);
    }

    for (int t = 0; t < 2; ++t) {
        {
            uint32_t h[8], l[8];
#pragma unroll
            for (int j = 0; j < 8; ++j) {
                h[j] = cvt_bf2(af[2 * j], af[2 * j + 1]);
                l[j] = cvt_bf2_lo(h[j], af[2 * j], af[2 * j + 1]);
            }
            *(uint4*)&sAH[ar][as_]     = make_uint4(h[0], h[1], h[2], h[3]);
            *(uint4*)&sAH[ar][as_ + 8] = make_uint4(h[4], h[5], h[6], h[7]);
            *(uint4*)&sAL[ar][as_]     = make_uint4(l[0], l[1], l[2], l[3]);
            *(uint4*)&sAL[ar][as_ + 8] = make_uint4(l[4], l[5], l[6], l[7]);
#pragma unroll
            for (int j = 0; j < 8; ++j) {
                h[j] = cvt_bf2(bf[2 * j], bf[2 * j + 1]);
                l[j] = cvt_bf2_lo(h[j], bf[2 * j], bf[2 * j + 1]);
            }
            *(uint4*)&sBH[br][bs]     = make_uint4(h[0], h[1], h[2], h[3]);
            *(uint4*)&sBH[br][bs + 8] = make_uint4(h[4], h[5], h[6], h[7]);
            *(uint4*)&sBL[br][bs]     = make_uint4(l[0], l[1], l[2], l[3]);
            *(uint4*)&sBL[br][bs + 8] = make_uint4(l[4], l[5], l[6], l[7]);
        }
        if (t + 1 < 2) {
            const int kt = k0 + 64;
            const float* ap = A + (size_t)ar * NN + kt + as_;
#pragma unroll
            for (int w = 0; w < 4; ++w)
                *(float4*)&af[4 * w] = __ldg((const float4*)ap + w);
#pragma unroll
            for (int p = 1; p < KSM1; ++p) {
                const float* ap2 = ap + (size_t)p * (BB * NN);
#pragma unroll
                for (int w = 0; w < 4; ++w) {
                    float4 tt = __ldg((const float4*)ap2 + w);
                    af[4 * w + 0] += tt.x; af[4 * w + 1] += tt.y;
                    af[4 * w + 2] += tt.z; af[4 * w + 3] += tt.w;
                }
            }
            const float* bp = Bsrc + (size_t)(kt + br) * HN + n0 + bs;
#pragma unroll
            for (int w = 0; w < 4; ++w)
                *(float4*)&bf[4 * w] = __ldg((const float4*)bp + w);
        }
        __syncthreads();

#pragma unroll
        for (int ks = 0; ks < 4; ++ks) {
            uint32_t a0[4], a1[4], b0[4], b1[4], c0[4], c1[4];
            ldmat4(a0, aH_b + ks * 32);
            ldmat4(a1, aL_b + ks * 32);
            ldmat4t(b0, bH_b + (uint32_t)(ks * 16 * PAD * 2));
            ldmat4t(b1, bH_b + (uint32_t)(ks * 16 * PAD * 2) + 32);
            ldmat4t(c0, bL_b + (uint32_t)(ks * 16 * PAD * 2));
            ldmat4t(c1, bL_b + (uint32_t)(ks * 16 * PAD * 2) + 32);
            mma16816(acc[0], a0, b0[0], b0[1]);
            mma16816(acc[1], a0, b0[2], b0[3]);
            mma16816(acc[2], a0, b1[0], b1[1]);
            mma16816(acc[3], a0, b1[2], b1[3]);
            mma16816(acc[0], a0, c0[0], c0[1]);
            mma16816(acc[1], a0, c0[2], c0[3]);
            mma16816(acc[2], a0, c1[0], c1[1]);
            mma16816(acc[3], a0, c1[2], c1[3]);
            mma16816(acc[0], a1, b0[0], b0[1]);
            mma16816(acc[1], a1, b0[2], b0[3]);
            mma16816(acc[2], a1, b1[0], b1[1]);
            mma16816(acc[3], a1, b1[2], b1[3]);
        }
        __syncthreads();
    }

    float* C = Cp + (size_t)blockIdx.y * (64ull * HN);
    const int g = lane >> 2, tig = lane & 3;
#pragma unroll
    for (int j = 0; j < 4; ++j) {
        const int col = n0 + nw * 32 + j * 8 + tig * 2;
        const int r0 = mw * 16 + g;
        float2 o0 = {acc[j][0], acc[j][1]};
        float2 o1 = {acc[j][2], acc[j][3]};
        *(float2*)&C[(size_t)r0 * HN + col]       = o0;
        *(float2*)&C[(size_t)(r0 + 8) * HN + col] = o1;
    }
}

// ---------------- validate: float4 loads, 4 threads/output-quad ------------
// blocks 0..63: each handles 64 float4 outputs; 4 threads per float4, each
// sums 8 slabs with independent LDG.128 (high MLP). block 64: bias checks.
__global__ void __launch_bounds__(256) k_validate(const float* __restrict__ b0,
                                                  const float* __restrict__ b1,
                                                  const float* __restrict__ b2)
{
    __shared__ float4 red[192];
    const int tid = threadIdx.x;
    int bad = 0;
    if (blockIdx.x < 64) {
        const int o = tid & 63;
        const int o4 = blockIdx.x * 64 + o;      // float4 index, 4096 total
        const int q = tid >> 6;                  // 0..3 -> slab quarters
        const float4* P = (const float4*)d_x0p;
        float4 s = {0.f, 0.f, 0.f, 0.f};
#pragma unroll
        for (int p = 0; p < 8; ++p) {
            float4 t = P[(size_t)(q * 8 + p) * (BB * HN / 4) + o4];
            s.x += t.x; s.y += t.y; s.z += t.z; s.w += t.w;
        }
        if (q) red[(q - 1) * 64 + o] = s;
        __syncthreads();
        if (!q) {
            const float4 a = red[o], b = red[64 + o], c = red[128 + o];
            const float4 bb = __ldg((const float4*)b0 + (o4 & 63));
            const float v0 = ((s.x + a.x) + (b.x + c.x)) + bb.x;
            const float v1 = ((s.y + a.y) + (b.y + c.y)) + bb.y;
            const float v2 = ((s.z + a.z) + (b.z + c.z)) + bb.z;
            const float v3 = ((s.w + a.w) + (b.w + c.w)) + bb.w;
            bad = (v0 >= X_LIMIT_TENSOR) | (v1 >= X_LIMIT_TENSOR) |
                  (v2 >= X_LIMIT_TENSOR) | (v3 >= X_LIMIT_TENSOR);
        }
    } else {
        bad = (__ldg(b1 + tid) >= X_LIMIT_EXACT) ||
              (__ldg(b2 + tid) >= X_LIMIT_EXACT);
        __syncthreads();
    }
    if (__syncthreads_or(bad) && tid == 0) atomicOr(&d_need_slow, 1u);
}

// ---------------- exact fallback persistent path (guarded) ----------------
__device__ __forceinline__ int stage_to_smem(const float* __restrict__ src,
                                             float* __restrict__ s_x, int tid) {
    const float4* s4 = (const float4*)src;
    float4* dd = (float4*)s_x;
    int flag = 0;
#pragma unroll
    for (int it = 0; it < 16; ++it) {
        const int i = tid + it * 256;
        float4 v = __ldcg(s4 + i);
        flag |= (v.x != 0.f) | (v.y != 0.f) | (v.z != 0.f) | (v.w != 0.f);
        dd[i] = v;
    }
    return flag;
}

__device__ __forceinline__ void gemm_phase(const float* __restrict__ sp,
                                           const float* __restrict__ W,
                                           const float* __restrict__ bias,
                                           float* __restrict__ xout,
                                           int bid, int tid,
                                           float* s_rows, float* s_psum) {
    int flag = 0;
#pragma unroll
    for (int it = 0; it < 2; ++it) {
        const int i = tid + it * 256;
        const float v = __ldcg(sp + bid * 512 + i);
        flag |= (v != 0.f);
        s_rows[i] = v;
    }
    const int tx = tid & 63;
    const int ty = tid >> 6;
    const int c0 = tx * 4;
    const int kb = ty * 64;
    const int any = __syncthreads_or(flag);

    if (any) {
        float4 a0 = {0.f, 0.f, 0.f, 0.f}, a1 = {0.f, 0.f, 0.f, 0.f};
        const float* s0 = s_rows + kb;
        const float* s1 = s_rows + 256 + kb;
#pragma unroll 8
        for (int k = 0; k < 64; ++k) {
            float4 ww = __ldg((const float4*)(W + (size_t)(kb + k) * 256 + c0));
            const float u0 = s0[k], u1 = s1[k];
            a0.x += u0 * ww.x; a0.y += u0 * ww.y; a0.z += u0 * ww.z; a0.w += u0 * ww.w;
            a1.x += u1 * ww.x; a1.y += u1 * ww.y; a1.z += u1 * ww.z; a1.w += u1 * ww.w;
        }
        *(float4*)&s_psum[(ty * 2 + 0) * 256 + c0] = a0;
        *(float4*)&s_psum[(ty * 2 + 1) * 256 + c0] = a1;
        __syncthreads();
        if (ty == 0) {
#pragma unroll
            for (int r = 0; r < 2; ++r) {
                float4 p0 = *(float4*)&s_psum[(0 + r) * 256 + c0];
                float4 p1 = *(float4*)&s_psum[(2 + r) * 256 + c0];
                float4 p2 = *(float4*)&s_psum[(4 + r) * 256 + c0];
                float4 p3 = *(float4*)&s_psum[(6 + r) * 256 + c0];
                float4 bbv = __ldg((const float4*)(bias + c0));
                float4 o;
                o.x = ((p0.x + p1.x) + (p2.x + p3.x)) + bbv.x;
                o.y = ((p0.y + p1.y) + (p2.y + p3.y)) + bbv.y;
                o.z = ((p0.z + p1.z) + (p2.z + p3.z)) + bbv.z;
                o.w = ((p0.w + p1.w) + (p2.w + p3.w)) + bbv.w;
                *(float4*)(xout + (size_t)(bid * 2 + r) * 256 + c0) = o;
            }
        }
        __syncthreads();
    } else {
        if (ty == 0) {
            float4 bbv = __ldg((const float4*)(bias + c0));
#pragma unroll
            for (int r = 0; r < 2; ++r)
                *(float4*)(xout + (size_t)(bid * 2 + r) * 256 + c0) = bbv;
        }
        __syncthreads();
    }
}

__device__ __forceinline__ void lif_scan_layer(const float* __restrict__ xin,
                                               float* __restrict__ spout,
                                               float& v, float& isyn, float& refr,
                                               int tid, float* s_x) {
    int flag = stage_to_smem(xin, s_x, tid);
    flag |= (v != V_REST_C) | (isyn != 0.f) | (refr != 0.f);
    const int any = __syncthreads_or(flag);
    if (any) {
        float nxt = s_x[tid];
#pragma unroll 4
        for (int b = 0; b < 64; ++b) {
            const float ib = nxt;
            if (b < 63) nxt = s_x[(b + 1) * 256 + tid];
            float sp;
            lif_step(v, isyn, refr, ib, sp);
            spout[b * 256 + tid] = sp;
        }
    } else {
        const float4 z = {0.f, 0.f, 0.f, 0.f};
        float4* o4 = (float4*)spout;
#pragma unroll
        for (int it = 0; it < 16; ++it) o4[tid + it * 256] = z;
    }
    __syncthreads();
}

// Exact persistent simulation. Guarded prologue recomputes x0 in exact fp32
// from the raw inputs (naive smem-staged GEMM; never taken on the fast path).
__global__ void __launch_bounds__(256) k_persist_slow(
    const float* __restrict__ spikes, const float* __restrict__ adj,
    const float* __restrict__ W0, const float* __restrict__ b0,
    const float* __restrict__ W1, const float* __restrict__ b1,
    const float* __restrict__ W2, const float* __restrict__ b2,
    float* __restrict__ traces)
{
    if (atomicOr(&d_need_slow, 0u) == 0u) return;

    extern __shared__ float sh[];
    float* s_x    = sh;                     // 16384 floats
    float* s_rows = sh + 16384;
    float* s_psum = sh + 16896;
    const int tid = threadIdx.x;
    const int bid = blockIdx.x;

    // ---- exact x0 for rows bid*2 .. bid*2+1 (slow, correct, never taken) ----
    {
        const int r0 = bid * 2;
        // spikes rows -> s_x[0..8192)
        for (int j = tid; j < 2 * NN; j += 256)
            s_x[j] = __ldg(spikes + (size_t)(r0 + (j >> 12)) * NN + (j & (NN - 1)));
        __syncthreads();
        // g rows -> s_x[8192..16384)
        for (int r = 0; r < 2; ++r) {
            const float* arow = s_x + r * NN;
            for (int i = 0; i < NN / 256; ++i) {
                const int n = tid + i * 256;
                float accv = 0.f;
                for (int k = 0; k < NN; ++k)
                    accv = fmaf(arow[k], __ldg(adj + (size_t)k * NN + n), accv);
                s_x[2 * NN + r * NN + n] = accv;
            }
        }
        __syncthreads();
        // x0 rows
        for (int r = 0; r < 2; ++r) {
            const float* grow = s_x + 2 * NN + r * NN;
            float accv = 0.f;
            for (int n = 0; n < NN; ++n)
                accv = fmaf(grow[n], __ldg(W0 + (size_t)n * HN + tid), accv);
            d_x0[(r0 + r) * HN + tid] = accv + __ldg(b0 + tid);
        }
    }
    gbar();

    float v0 = V_REST_C, i0 = 0.f, r0s = 0.f;
    float v1 = V_REST_C, i1 = 0.f, r1s = 0.f;
    float v2 = V_REST_C, i2 = 0.f, r2s = 0.f;
    const float* x0pre = d_x0;

    for (int t = 0; t < TT; ++t) {
        if (bid == 0) {
            float nxt = __ldg(x0pre + tid);
#pragma unroll 4
            for (int b = 0; b < 64; ++b) {
                const float ib = nxt;
                if (b < 63) nxt = __ldg(x0pre + (b + 1) * 256 + tid);
                float sp;
                lif_step(v0, i0, r0s, ib, sp);
                d_sp0[b * 256 + tid] = sp;
            }
        }
        gbar();
        gemm_phase(d_sp0, W1, b1, d_x1, bid, tid, s_rows, s_psum);
        gbar();
        if (bid == 0) lif_scan_layer(d_x1, d_sp1, v1, i1, r1s, tid, s_x);
        gbar();
        gemm_phase(d_sp1, W2, b2, d_x2, bid, tid, s_rows, s_psum);
        gbar();
        if (bid == 0) lif_scan_layer(d_x2, traces + (size_t)t * (BB * HN),
                                     v2, i2, r2s, tid, s_x);
    }
}

// ---------------- logits (guarded fast path) ----------------
__global__ void __launch_bounds__(256) k_logits(const float* __restrict__ traces,
                                                const float* __restrict__ Wp,
                                                const float* __restrict__ bp,
                                                float* __restrict__ out)
{
    __shared__ float hrow[HN];
    const int b = blockIdx.x;
    const int tid = threadIdx.x;
    if (*((volatile unsigned*)&d_need_slow) == 0u) {
        if (tid < 5) out[b * 5 + tid] = __ldg(bp + tid);
        return;
    }
    float s = 0.f;
    for (int t = 0; t < TT; ++t)
        s += traces[(size_t)t * (BB * HN) + b * HN + tid];
    hrow[tid] = __fdiv_rn(s, 100.0f);
    __syncthreads();
    if (tid < 5) {
        float acc = 0.f;
        for (int h = 0; h < HN; ++h)
            acc += hrow[h] * __ldg(Wp + h * 5 + tid);
        out[b * 5 + tid] = acc + __ldg(bp + tid);
    }
}

// ---------------- launch ----------------
extern "C" void kernel_launch(void* const* d_in, const int* in_sizes, int n_in,
                              void* d_out, int out_size) {
    const float* spikes = (const float*)d_in[0];
    const float* adj    = (const float*)d_in[1];
    const float* W0     = (const float*)d_in[2];
    const float* b0     = (const float*)d_in[3];
    const float* W1     = (const float*)d_in[4];
    const float* b1     = (const float*)d_in[5];
    const float* W2     = (const float*)d_in[6];
    const float* b2     = (const float*)d_in[7];
    const float* Wp     = (const float*)d_in[8];
    const float* bp     = (const float*)d_in[9];
    float* out = (float*)d_out;        // [logits(64*5) | traces(100*64*256)]
    float* traces = out + BB * 5;

    const int smem_slow = (16384 + 512 + 2048) * (int)sizeof(float);
    const int smem_g1   = 2 * 3 * 64 * PAD * 2;      // 55296 B
    cudaFuncSetAttribute(k_persist_slow, cudaFuncAttributeMaxDynamicSharedMemorySize,
                         smem_slow);
    cudaFuncSetAttribute(k_g1, cudaFuncAttributeMaxDynamicSharedMemorySize,
                         smem_g1);

    void* p;
    cudaGetSymbolAddress(&p, d_gA);   float* gA  = (float*)p;
    cudaGetSymbolAddress(&p, d_x0p);  float* x0p = (float*)p;
    cudaGetSymbolAddress(&p, d_spH);  __nv_bfloat16* spH = (__nv_bfloat16*)p;
    cudaGetSymbolAddress(&p, d_spL);  __nv_bfloat16* spL = (__nv_bfloat16*)p;

    // prep: zero traces + reset flag + split spikes to bf16 hi/lo
    k_prep<<<400, 256>>>(traces, spikes);
    // tensor GEMM1 (2-term): g partials(8) = spikes(split) @ adj
    k_g1<<<dim3(NN / 64, KSM1), 256, smem_g1>>>(spH, spL, adj, gA);
    // tensor GEMM2 (3-term): x0 partials(32) = (sum 8 slabs) @ W0
    k_g2<<<dim3(HN / 64, KSM2), 256>>>(gA, W0, x0p);
    // no-spike validation (approx x0 bound + bias bounds)
    k_validate<<<65, 256>>>(b0, b1, b2);
    // exact persistent simulation (guarded: recomputes exact x0 in prologue;
    // early-exits when certified spike-free)
    k_persist_slow<<<GBLK, 256, smem_slow>>>(spikes, adj, W0, b0,
                                             W1, b1, W2, b2, traces);
    // policy head (fast path writes bp directly)
    k_logits<<<BB, 256>>>(traces, Wp, bp, out);
}

// round 15
// speedup vs baseline: 1.5171x; 1.0868x over previous
#include <cuda_runtime.h>
#include <cuda_bf16.h>
#include <cstdint>

// ---------------- problem constants ----------------
#define HN    256
#define BB    64
#define NN    4096
#define TT    100
#define GBLK  32
#define PAD   72          // bf16 elements per smem row (144 B)

#define V_REST_C   (-70.0f)
#define V_RESET_C  (-75.0f)
#define V_THRESH_C (-55.0f)
#define X_LIMIT_EXACT  2.5f
#define X_LIMIT_TENSOR 2.4f

#define KSM1 8      // mma GEMM1 k-split (Kchunk 512)
#define KSM2 32     // GEMM2 k-split (Kchunk 128)

// ---------------- static device scratch ----------------
__device__ float d_gA[KSM1 * BB * NN];       // GEMM1 mma partials (8 slabs)
__device__ float d_x0p[KSM2 * BB * HN];
__device__ float d_x0[BB * HN];
__device__ __nv_bfloat16 d_spH[BB * NN];     // spikes bf16 (hi)
__device__ float d_sp0[BB * HN];
__device__ float d_sp1[BB * HN];
__device__ float d_x1[BB * HN];
__device__ float d_x2[BB * HN];
__device__ unsigned d_barcount;
__device__ unsigned d_bargen;
__device__ unsigned d_need_slow;

// ---------------- helpers ----------------
__device__ __forceinline__ uint32_t cvt_bf2(float x0, float x1) {
    uint32_t r;
    asm("cvt.rn.bf16x2.f32 %0, %1, %2;" : "=r"(r) : "f"(x1), "f"(x0));
    return r;
}
__device__ __forceinline__ uint32_t cvt_bf2_lo(uint32_t h, float x0, float x1) {
    const float d0 = x0 - __uint_as_float(h << 16);
    const float d1 = x1 - __uint_as_float(h & 0xffff0000u);
    return cvt_bf2(d0, d1);
}
__device__ __forceinline__ void cpasync16(uint32_t dst, const void* src) {
    asm volatile("cp.async.cg.shared.global [%0], [%1], 16;" :: "r"(dst), "l"(src));
}
__device__ __forceinline__ void cpasync_commit() {
    asm volatile("cp.async.commit_group;" ::: "memory");
}
template <int N>
__device__ __forceinline__ void cpasync_wait() {
    asm volatile("cp.async.wait_group %0;" :: "n"(N) : "memory");
}
__device__ __forceinline__ void ldmat4(uint32_t* r, uint32_t addr) {
    asm volatile("ldmatrix.sync.aligned.m8n8.x4.shared.b16 {%0,%1,%2,%3}, [%4];"
                 : "=r"(r[0]), "=r"(r[1]), "=r"(r[2]), "=r"(r[3]) : "r"(addr));
}
__device__ __forceinline__ void ldmat4t(uint32_t* r, uint32_t addr) {
    asm volatile("ldmatrix.sync.aligned.m8n8.x4.trans.shared.b16 {%0,%1,%2,%3}, [%4];"
                 : "=r"(r[0]), "=r"(r[1]), "=r"(r[2]), "=r"(r[3]) : "r"(addr));
}
__device__ __forceinline__ void mma16816(float* c, const uint32_t* a,
                                         uint32_t b0, uint32_t b1) {
    asm volatile(
        "mma.sync.aligned.m16n8k16.row.col.f32.bf16.bf16.f32 "
        "{%0,%1,%2,%3}, {%4,%5,%6,%7}, {%8,%9}, {%0,%1,%2,%3};"
        : "+f"(c[0]), "+f"(c[1]), "+f"(c[2]), "+f"(c[3])
        : "r"(a[0]), "r"(a[1]), "r"(a[2]), "r"(a[3]), "r"(b0), "r"(b1));
}

// ---------------- LIF micro-step ----------------
__device__ __forceinline__ void lif_step(float& v, float& isyn, float& refr,
                                         float ib, float& sp) {
    const bool  in_refr = refr > 0.0f;
    const float isyn_u  = isyn + (ib - isyn * 0.2f);
    const float v_u     = v + (isyn_u - (v - V_REST_C)) * 0.05f;
    const bool  spike   = (!in_refr) && (v_u >= V_THRESH_C);
    v    = in_refr ? v    : (spike ? V_RESET_C : v_u);
    isyn = in_refr ? isyn : isyn_u;
    refr = in_refr ? (refr - 1.0f) : (spike ? 2.0f : refr);
    sp   = spike ? 1.0f : 0.0f;
}

// ---------------- grid barrier ----------------
__device__ __forceinline__ void gbar() {
    __syncthreads();
    if (threadIdx.x == 0) {
        __threadfence();
        unsigned gen = *((volatile unsigned*)&d_bargen);
        if (atomicAdd(&d_barcount, 1u) == GBLK - 1u) {
            d_barcount = 0u;
            __threadfence();
            atomicAdd(&d_bargen, 1u);
        } else {
            while (*((volatile unsigned*)&d_bargen) == gen) { }
        }
        __threadfence();
    }
    __syncthreads();
}

// ---------------- prep: zero traces + reset flag + spikes->bf16 ------------
__global__ void __launch_bounds__(256) k_prep(float* __restrict__ traces,
                                              const float* __restrict__ spikes) {
    if (blockIdx.x == 0 && threadIdx.x == 0) d_need_slow = 0u;
    const float4 z = {0.f, 0.f, 0.f, 0.f};
    float4* t4 = (float4*)traces;
    int i = blockIdx.x * 256 + threadIdx.x;
    const int stride = gridDim.x * 256;
    const int n4 = (TT * BB * HN) / 4;
    for (int j = i; j < n4; j += stride) t4[j] = z;
    if (blockIdx.x < 256) {           // convert spikes (65536 float4s)
        const int i4 = blockIdx.x * 256 + threadIdx.x;
        float4 v = __ldg((const float4*)spikes + i4);
        uint2 h;
        h.x = cvt_bf2(v.x, v.y);
        h.y = cvt_bf2(v.z, v.w);
        ((uint2*)d_spH)[i4] = h;
    }
}

// ---------------- GEMM1: g partials = spikes(bf16) @ adj (1-term hh) --------
// BM=64, BN=64, BK=64, Kchunk=512 (T=8), grid (64, 8), 256 thr = 8 warps.
// Same geometry as verified config; AL stream + al mma deleted (pure removal).
__global__ void __launch_bounds__(256) k_g1(
    const __nv_bfloat16* __restrict__ AH,
    const float* __restrict__ Bsrc, float* __restrict__ Cp)
{
    extern __shared__ __align__(16) char sm[];
    const uint32_t smBase = (uint32_t)__cvta_generic_to_shared(sm);
    const int AB  = 64 * PAD * 2;        // 9216 B per array
    const int BUF = 2 * AB;              // AH | BH
    const int tid = threadIdx.x;
    const int warp = tid >> 5, lane = tid & 31;
    const int mw = warp & 3, nw = warp >> 2;
    const int n0 = blockIdx.x * 64;
    const int k0 = blockIdx.y * 512;

    float acc[4][4];
#pragma unroll
    for (int j = 0; j < 4; ++j)
#pragma unroll
        for (int c = 0; c < 4; ++c) acc[j][c] = 0.f;

    const int u0 = tid * 2;
    const int br = tid >> 2, bs = (tid & 3) * 16;

    const int lm_m = lane >> 3, lm_r = lane & 7;
    const uint32_t aOff = (uint32_t)(((mw * 16 + (lm_m & 1) * 8 + lm_r) * PAD
                                      + (lm_m >> 1) * 8) * 2);
    const uint32_t bOff = (uint32_t)((((lm_m & 1) * 8 + lm_r) * PAD
                                      + nw * 32 + (lm_m >> 1) * 8) * 2);

    float bf[16];
    {
#pragma unroll
        for (int q = 0; q < 2; ++q) {
            const int u = u0 + q, row = u >> 3, seg = u & 7;
            const uint32_t d = smBase + (uint32_t)((row * PAD + seg * 8) * 2);
            cpasync16(d, AH + (size_t)row * NN + k0 + seg * 8);
        }
        cpasync_commit();
        const float* bp = Bsrc + (size_t)(k0 + br) * NN + n0 + bs;
#pragma unroll
        for (int w = 0; w < 4; ++w) *(float4*)&bf[4 * w] = __ldg((const float4*)bp + w);
    }

    for (int t = 0; t < 8; ++t) {
        const int cur = t & 1;
        {
            uint32_t h[8];
#pragma unroll
            for (int j = 0; j < 8; ++j) h[j] = cvt_bf2(bf[2 * j], bf[2 * j + 1]);
            char* dst = sm + cur * BUF + AB + (br * PAD + bs) * 2;
            *(uint4*)dst        = make_uint4(h[0], h[1], h[2], h[3]);
            *(uint4*)(dst + 16) = make_uint4(h[4], h[5], h[6], h[7]);
        }
        if (t + 1 < 8) {
            const int kt = k0 + (t + 1) * 64;
#pragma unroll
            for (int q = 0; q < 2; ++q) {
                const int u = u0 + q, row = u >> 3, seg = u & 7;
                const uint32_t d = smBase + (uint32_t)((cur ^ 1) * BUF)
                                 + (uint32_t)((row * PAD + seg * 8) * 2);
                cpasync16(d, AH + (size_t)row * NN + kt + seg * 8);
            }
            cpasync_commit();
            const float* bp = Bsrc + (size_t)(kt + br) * NN + n0 + bs;
#pragma unroll
            for (int w = 0; w < 4; ++w)
                *(float4*)&bf[4 * w] = __ldg((const float4*)bp + w);
            cpasync_wait<1>();
        } else {
            cpasync_wait<0>();
        }
        __syncthreads();

        const uint32_t aH_b = smBase + (uint32_t)(cur * BUF) + aOff;
        const uint32_t bH_b = smBase + (uint32_t)(cur * BUF + AB) + bOff;
#pragma unroll
        for (int ks = 0; ks < 4; ++ks) {
            uint32_t a0[4], b0[4], b1[4];
            ldmat4(a0, aH_b + ks * 32);
            ldmat4t(b0, bH_b + (uint32_t)(ks * 16 * PAD * 2));
            ldmat4t(b1, bH_b + (uint32_t)(ks * 16 * PAD * 2) + 32);
            mma16816(acc[0], a0, b0[0], b0[1]);
            mma16816(acc[1], a0, b0[2], b0[3]);
            mma16816(acc[2], a0, b1[0], b1[1]);
            mma16816(acc[3], a0, b1[2], b1[3]);
        }
        __syncthreads();
    }

    float* C = Cp + (size_t)blockIdx.y * (64ull * NN);
    const int g = lane >> 2, tig = lane & 3;
#pragma unroll
    for (int j = 0; j < 4; ++j) {
        const int col = n0 + nw * 32 + j * 8 + tig * 2;
        const int r0 = mw * 16 + g;
        float2 o0 = {acc[j][0], acc[j][1]};
        float2 o1 = {acc[j][2], acc[j][3]};
        *(float2*)&C[(size_t)r0 * NN + col]       = o0;
        *(float2*)&C[(size_t)(r0 + 8) * NN + col] = o1;
    }
}

// ---------------- GEMM2: x0 partials = (sum 8 g slabs) @ W0 (3-term) --------
// BM=64, BN=64, BK=64, Kchunk=128 (T=2), grid (4, 32).  (verified — unchanged)
__global__ void __launch_bounds__(256) k_g2(
    const float* __restrict__ A, const float* __restrict__ Bsrc,
    float* __restrict__ Cp)
{
    __shared__ __align__(16) __nv_bfloat16 sAH[64][PAD];
    __shared__ __align__(16) __nv_bfloat16 sAL[64][PAD];
    __shared__ __align__(16) __nv_bfloat16 sBH[64][PAD];
    __shared__ __align__(16) __nv_bfloat16 sBL[64][PAD];
    const int tid = threadIdx.x;
    const int warp = tid >> 5, lane = tid & 31;
    const int mw = warp & 3, nw = warp >> 2;
    const int n0 = blockIdx.x * 64;
    const int k0 = blockIdx.y * 128;

    float acc[4][4];
#pragma unroll
    for (int j = 0; j < 4; ++j)
#pragma unroll
        for (int c = 0; c < 4; ++c) acc[j][c] = 0.f;

    const int ar = tid >> 2, as_ = (tid & 3) * 16;
    const int br = tid >> 2, bs = (tid & 3) * 16;

    const int lm_m = lane >> 3, lm_r = lane & 7;
    const uint32_t aOff = (uint32_t)(((mw * 16 + (lm_m & 1) * 8 + lm_r) * PAD
                                      + (lm_m >> 1) * 8) * 2);
    const uint32_t bOff = (uint32_t)((((lm_m & 1) * 8 + lm_r) * PAD
                                      + nw * 32 + (lm_m >> 1) * 8) * 2);
    const uint32_t aH_b = (uint32_t)__cvta_generic_to_shared(&sAH[0][0]) + aOff;
    const uint32_t aL_b = (uint32_t)__cvta_generic_to_shared(&sAL[0][0]) + aOff;
    const uint32_t bH_b = (uint32_t)__cvta_generic_to_shared(&sBH[0][0]) + bOff;
    const uint32_t bL_b = (uint32_t)__cvta_generic_to_shared(&sBL[0][0]) + bOff;

    float af[16], bf[16];
    {
        const float* ap = A + (size_t)ar * NN + k0 + as_;
#pragma unroll
        for (int w = 0; w < 4; ++w) *(float4*)&af[4 * w] = __ldg((const float4*)ap + w);
#pragma unroll
        for (int p = 1; p < KSM1; ++p) {
            const float* ap2 = ap + (size_t)p * (BB * NN);
#pragma unroll
            for (int w = 0; w < 4; ++w) {
                float4 t = __ldg((const float4*)ap2 + w);
                af[4 * w + 0] += t.x; af[4 * w + 1] += t.y;
                af[4 * w + 2] += t.z; af[4 * w + 3] += t.w;
            }
        }
        const float* bp = Bsrc + (size_t)(k0 + br) * HN + n0 + bs;
#pragma unroll
        for (int w = 0; w < 4; ++w) *(float4*)&bf[4 * w] = __ldg((const float4*)bp + w);
    }

    for (int t = 0; t < 2; ++t) {
        {
            uint32_t h[8], l[8];
#pragma unroll
            for (int j = 0; j < 8; ++j) {
                h[j] = cvt_bf2(af[2 * j], af[2 * j + 1]);
                l[j] = cvt_bf2_lo(h[j], af[2 * j], af[2 * j + 1]);
            }
            *(uint4*)&sAH[ar][as_]     = make_uint4(h[0], h[1], h[2], h[3]);
            *(uint4*)&sAH[ar][as_ + 8] = make_uint4(h[4], h[5], h[6], h[7]);
            *(uint4*)&sAL[ar][as_]     = make_uint4(l[0], l[1], l[2], l[3]);
            *(uint4*)&sAL[ar][as_ + 8] = make_uint4(l[4], l[5], l[6], l[7]);
#pragma unroll
            for (int j = 0; j < 8; ++j) {
                h[j] = cvt_bf2(bf[2 * j], bf[2 * j + 1]);
                l[j] = cvt_bf2_lo(h[j], bf[2 * j], bf[2 * j + 1]);
            }
            *(uint4*)&sBH[br][bs]     = make_uint4(h[0], h[1], h[2], h[3]);
            *(uint4*)&sBH[br][bs + 8] = make_uint4(h[4], h[5], h[6], h[7]);
            *(uint4*)&sBL[br][bs]     = make_uint4(l[0], l[1], l[2], l[3]);
            *(uint4*)&sBL[br][bs + 8] = make_uint4(l[4], l[5], l[6], l[7]);
        }
        if (t + 1 < 2) {
            const int kt = k0 + 64;
            const float* ap = A + (size_t)ar * NN + kt + as_;
#pragma unroll
            for (int w = 0; w < 4; ++w)
                *(float4*)&af[4 * w] = __ldg((const float4*)ap + w);
#pragma unroll
            for (int p = 1; p < KSM1; ++p) {
                const float* ap2 = ap + (size_t)p * (BB * NN);
#pragma unroll
                for (int w = 0; w < 4; ++w) {
                    float4 tt = __ldg((const float4*)ap2 + w);
                    af[4 * w + 0] += tt.x; af[4 * w + 1] += tt.y;
                    af[4 * w + 2] += tt.z; af[4 * w + 3] += tt.w;
                }
            }
            const float* bp = Bsrc + (size_t)(kt + br) * HN + n0 + bs;
#pragma unroll
            for (int w = 0; w < 4; ++w)
                *(float4*)&bf[4 * w] = __ldg((const float4*)bp + w);
        }
        __syncthreads();

#pragma unroll
        for (int ks = 0; ks < 4; ++ks) {
            uint32_t a0[4], a1[4], b0[4], b1[4], c0[4], c1[4];
            ldmat4(a0, aH_b + ks * 32);
            ldmat4(a1, aL_b + ks * 32);
            ldmat4t(b0, bH_b + (uint32_t)(ks * 16 * PAD * 2));
            ldmat4t(b1, bH_b + (uint32_t)(ks * 16 * PAD * 2) + 32);
            ldmat4t(c0, bL_b + (uint32_t)(ks * 16 * PAD * 2));
            ldmat4t(c1, bL_b + (uint32_t)(ks * 16 * PAD * 2) + 32);
            mma16816(acc[0], a0, b0[0], b0[1]);
            mma16816(acc[1], a0, b0[2], b0[3]);
            mma16816(acc[2], a0, b1[0], b1[1]);
            mma16816(acc[3], a0, b1[2], b1[3]);
            mma16816(acc[0], a0, c0[0], c0[1]);
            mma16816(acc[1], a0, c0[2], c0[3]);
            mma16816(acc[2], a0, c1[0], c1[1]);
            mma16816(acc[3], a0, c1[2], c1[3]);
            mma16816(acc[0], a1, b0[0], b0[1]);
            mma16816(acc[1], a1, b0[2], b0[3]);
            mma16816(acc[2], a1, b1[0], b1[1]);
            mma16816(acc[3], a1, b1[2], b1[3]);
        }
        __syncthreads();
    }

    float* C = Cp + (size_t)blockIdx.y * (64ull * HN);
    const int g = lane >> 2, tig = lane & 3;
#pragma unroll
    for (int j = 0; j < 4; ++j) {
        const int col = n0 + nw * 32 + j * 8 + tig * 2;
        const int r0 = mw * 16 + g;
        float2 o0 = {acc[j][0], acc[j][1]};
        float2 o1 = {acc[j][2], acc[j][3]};
        *(float2*)&C[(size_t)r0 * HN + col]       = o0;
        *(float2*)&C[(size_t)(r0 + 8) * HN + col] = o1;
    }
}

// ---------------- validate: 257 blocks, 2 slabs/thread (high MLP) ----------
// blocks 0..255: 16 float4 outputs each; 16 threads per quad, each sums 2
// slabs; smem tree combine. block 256: bias checks.
__global__ void __launch_bounds__(256) k_validate(const float* __restrict__ b0,
                                                  const float* __restrict__ b1,
                                                  const float* __restrict__ b2)
{
    __shared__ float4 red[256];
    const int tid = threadIdx.x;
    int bad = 0;
    if (blockIdx.x < 256) {
        const int o = tid & 15;                  // quad within block
        const int o4 = blockIdx.x * 16 + o;      // float4 index (4096 total)
        const int q = tid >> 4;                  // 0..15 slab pair
        const float4* P = (const float4*)d_x0p;
        float4 t0 = P[(size_t)(2 * q + 0) * (BB * HN / 4) + o4];
        float4 t1 = P[(size_t)(2 * q + 1) * (BB * HN / 4) + o4];
        float4 s = {t0.x + t1.x, t0.y + t1.y, t0.z + t1.z, t0.w + t1.w};
        red[tid] = s;
        __syncthreads();
        // tree combine over q (stride halving in q-major layout: q*16 + o)
#pragma unroll
        for (int st = 8; st >= 1; st >>= 1) {
            if (q < st) {
                float4 a = red[q * 16 + o], b = red[(q + st) * 16 + o];
                a.x += b.x; a.y += b.y; a.z += b.z; a.w += b.w;
                red[q * 16 + o] = a;
            }
            __syncthreads();
        }
        if (q == 0) {
            float4 s0 = red[o];
            const float4 bb = __ldg((const float4*)b0 + (o4 & 63));
            bad = (s0.x + bb.x >= X_LIMIT_TENSOR) | (s0.y + bb.y >= X_LIMIT_TENSOR) |
                  (s0.z + bb.z >= X_LIMIT_TENSOR) | (s0.w + bb.w >= X_LIMIT_TENSOR);
        }
    } else {
        bad = (__ldg(b1 + tid) >= X_LIMIT_EXACT) ||
              (__ldg(b2 + tid) >= X_LIMIT_EXACT);
    }
    if (__syncthreads_or(bad) && tid == 0) atomicOr(&d_need_slow, 1u);
}

// ---------------- exact fallback persistent path (guarded) ----------------
__device__ __forceinline__ int stage_to_smem(const float* __restrict__ src,
                                             float* __restrict__ s_x, int tid) {
    const float4* s4 = (const float4*)src;
    float4* dd = (float4*)s_x;
    int flag = 0;
#pragma unroll
    for (int it = 0; it < 16; ++it) {
        const int i = tid + it * 256;
        float4 v = __ldcg(s4 + i);
        flag |= (v.x != 0.f) | (v.y != 0.f) | (v.z != 0.f) | (v.w != 0.f);
        dd[i] = v;
    }
    return flag;
}

__device__ __forceinline__ void gemm_phase(const float* __restrict__ sp,
                                           const float* __restrict__ W,
                                           const float* __restrict__ bias,
                                           float* __restrict__ xout,
                                           int bid, int tid,
                                           float* s_rows, float* s_psum) {
    int flag = 0;
#pragma unroll
    for (int it = 0; it < 2; ++it) {
        const int i = tid + it * 256;
        const float v = __ldcg(sp + bid * 512 + i);
        flag |= (v != 0.f);
        s_rows[i] = v;
    }
    const int tx = tid & 63;
    const int ty = tid >> 6;
    const int c0 = tx * 4;
    const int kb = ty * 64;
    const int any = __syncthreads_or(flag);

    if (any) {
        float4 a0 = {0.f, 0.f, 0.f, 0.f}, a1 = {0.f, 0.f, 0.f, 0.f};
        const float* s0 = s_rows + kb;
        const float* s1 = s_rows + 256 + kb;
#pragma unroll 8
        for (int k = 0; k < 64; ++k) {
            float4 ww = __ldg((const float4*)(W + (size_t)(kb + k) * 256 + c0));
            const float u0 = s0[k], u1 = s1[k];
            a0.x += u0 * ww.x; a0.y += u0 * ww.y; a0.z += u0 * ww.z; a0.w += u0 * ww.w;
            a1.x += u1 * ww.x; a1.y += u1 * ww.y; a1.z += u1 * ww.z; a1.w += u1 * ww.w;
        }
        *(float4*)&s_psum[(ty * 2 + 0) * 256 + c0] = a0;
        *(float4*)&s_psum[(ty * 2 + 1) * 256 + c0] = a1;
        __syncthreads();
        if (ty == 0) {
#pragma unroll
            for (int r = 0; r < 2; ++r) {
                float4 p0 = *(float4*)&s_psum[(0 + r) * 256 + c0];
                float4 p1 = *(float4*)&s_psum[(2 + r) * 256 + c0];
                float4 p2 = *(float4*)&s_psum[(4 + r) * 256 + c0];
                float4 p3 = *(float4*)&s_psum[(6 + r) * 256 + c0];
                float4 bbv = __ldg((const float4*)(bias + c0));
                float4 o;
                o.x = ((p0.x + p1.x) + (p2.x + p3.x)) + bbv.x;
                o.y = ((p0.y + p1.y) + (p2.y + p3.y)) + bbv.y;
                o.z = ((p0.z + p1.z) + (p2.z + p3.z)) + bbv.z;
                o.w = ((p0.w + p1.w) + (p2.w + p3.w)) + bbv.w;
                *(float4*)(xout + (size_t)(bid * 2 + r) * 256 + c0) = o;
            }
        }
        __syncthreads();
    } else {
        if (ty == 0) {
            float4 bbv = __ldg((const float4*)(bias + c0));
#pragma unroll
            for (int r = 0; r < 2; ++r)
                *(float4*)(xout + (size_t)(bid * 2 + r) * 256 + c0) = bbv;
        }
        __syncthreads();
    }
}

__device__ __forceinline__ void lif_scan_layer(const float* __restrict__ xin,
                                               float* __restrict__ spout,
                                               float& v, float& isyn, float& refr,
                                               int tid, float* s_x) {
    int flag = stage_to_smem(xin, s_x, tid);
    flag |= (v != V_REST_C) | (isyn != 0.f) | (refr != 0.f);
    const int any = __syncthreads_or(flag);
    if (any) {
        float nxt = s_x[tid];
#pragma unroll 4
        for (int b = 0; b < 64; ++b) {
            const float ib = nxt;
            if (b < 63) nxt = s_x[(b + 1) * 256 + tid];
            float sp;
            lif_step(v, isyn, refr, ib, sp);
            spout[b * 256 + tid] = sp;
        }
    } else {
        const float4 z = {0.f, 0.f, 0.f, 0.f};
        float4* o4 = (float4*)spout;
#pragma unroll
        for (int it = 0; it < 16; ++it) o4[tid + it * 256] = z;
    }
    __syncthreads();
}

// Exact persistent simulation. Guarded prologue recomputes x0 in exact fp32
// from the raw inputs (naive smem-staged GEMM; never taken on the fast path).
__global__ void __launch_bounds__(256) k_persist_slow(
    const float* __restrict__ spikes, const float* __restrict__ adj,
    const float* __restrict__ W0, const float* __restrict__ b0,
    const float* __restrict__ W1, const float* __restrict__ b1,
    const float* __restrict__ W2, const float* __restrict__ b2,
    float* __restrict__ traces)
{
    if (atomicOr(&d_need_slow, 0u) == 0u) return;

    extern __shared__ float sh[];
    float* s_x    = sh;
    float* s_rows = sh + 16384;
    float* s_psum = sh + 16896;
    const int tid = threadIdx.x;
    const int bid = blockIdx.x;

    // ---- exact x0 for rows bid*2 .. bid*2+1 (slow, correct, never taken) ----
    {
        const int r0 = bid * 2;
        for (int j = tid; j < 2 * NN; j += 256)
            s_x[j] = __ldg(spikes + (size_t)(r0 + (j >> 12)) * NN + (j & (NN - 1)));
        __syncthreads();
        for (int r = 0; r < 2; ++r) {
            const float* arow = s_x + r * NN;
            for (int i = 0; i < NN / 256; ++i) {
                const int n = tid + i * 256;
                float accv = 0.f;
                for (int k = 0; k < NN; ++k)
                    accv = fmaf(arow[k], __ldg(adj + (size_t)k * NN + n), accv);
                s_x[2 * NN + r * NN + n] = accv;
            }
        }
        __syncthreads();
        for (int r = 0; r < 2; ++r) {
            const float* grow = s_x + 2 * NN + r * NN;
            float accv = 0.f;
            for (int n = 0; n < NN; ++n)
                accv = fmaf(grow[n], __ldg(W0 + (size_t)n * HN + tid), accv);
            d_x0[(r0 + r) * HN + tid] = accv + __ldg(b0 + tid);
        }
    }
    gbar();

    float v0 = V_REST_C, i0 = 0.f, r0s = 0.f;
    float v1 = V_REST_C, i1 = 0.f, r1s = 0.f;
    float v2 = V_REST_C, i2 = 0.f, r2s = 0.f;
    const float* x0pre = d_x0;

    for (int t = 0; t < TT; ++t) {
        if (bid == 0) {
            float nxt = __ldg(x0pre + tid);
#pragma unroll 4
            for (int b = 0; b < 64; ++b) {
                const float ib = nxt;
                if (b < 63) nxt = __ldg(x0pre + (b + 1) * 256 + tid);
                float sp;
                lif_step(v0, i0, r0s, ib, sp);
                d_sp0[b * 256 + tid] = sp;
            }
        }
        gbar();
        gemm_phase(d_sp0, W1, b1, d_x1, bid, tid, s_rows, s_psum);
        gbar();
        if (bid == 0) lif_scan_layer(d_x1, d_sp1, v1, i1, r1s, tid, s_x);
        gbar();
        gemm_phase(d_sp1, W2, b2, d_x2, bid, tid, s_rows, s_psum);
        gbar();
        if (bid == 0) lif_scan_layer(d_x2, traces + (size_t)t * (BB * HN),
                                     v2, i2, r2s, tid, s_x);
    }
}

// ---------------- logits (guarded fast path) ----------------
__global__ void __launch_bounds__(256) k_logits(const float* __restrict__ traces,
                                                const float* __restrict__ Wp,
                                                const float* __restrict__ bp,
                                                float* __restrict__ out)
{
    __shared__ float hrow[HN];
    const int b = blockIdx.x;
    const int tid = threadIdx.x;
    if (*((volatile unsigned*)&d_need_slow) == 0u) {
        if (tid < 5) out[b * 5 + tid] = __ldg(bp + tid);
        return;
    }
    float s = 0.f;
    for (int t = 0; t < TT; ++t)
        s += traces[(size_t)t * (BB * HN) + b * HN + tid];
    hrow[tid] = __fdiv_rn(s, 100.0f);
    __syncthreads();
    if (tid < 5) {
        float acc = 0.f;
        for (int h = 0; h < HN; ++h)
            acc += hrow[h] * __ldg(Wp + h * 5 + tid);
        out[b * 5 + tid] = acc + __ldg(bp + tid);
    }
}

// ---------------- launch ----------------
extern "C" void kernel_launch(void* const* d_in, const int* in_sizes, int n_in,
                              void* d_out, int out_size) {
    const float* spikes = (const float*)d_in[0];
    const float* adj    = (const float*)d_in[1];
    const float* W0     = (const float*)d_in[2];
    const float* b0     = (const float*)d_in[3];
    const float* W1     = (const float*)d_in[4];
    const float* b1     = (const float*)d_in[5];
    const float* W2     = (const float*)d_in[6];
    const float* b2     = (const float*)d_in[7];
    const float* Wp     = (const float*)d_in[8];
    const float* bp     = (const float*)d_in[9];
    float* out = (float*)d_out;        // [logits(64*5) | traces(100*64*256)]
    float* traces = out + BB * 5;

    const int smem_slow = (16384 + 512 + 2048) * (int)sizeof(float);
    const int smem_g1   = 2 * 2 * 64 * PAD * 2;      // 36864 B (AH|BH x2 bufs)
    cudaFuncSetAttribute(k_persist_slow, cudaFuncAttributeMaxDynamicSharedMemorySize,
                         smem_slow);
    cudaFuncSetAttribute(k_g1, cudaFuncAttributeMaxDynamicSharedMemorySize,
                         smem_g1);

    void* p;
    cudaGetSymbolAddress(&p, d_gA);   float* gA  = (float*)p;
    cudaGetSymbolAddress(&p, d_x0p);  float* x0p = (float*)p;
    cudaGetSymbolAddress(&p, d_spH);  __nv_bfloat16* spH = (__nv_bfloat16*)p;

    // prep: zero traces + reset flag + spikes -> bf16
    k_prep<<<400, 256>>>(traces, spikes);
    // tensor GEMM1 (1-term hh): g partials(8) = spikes(bf16) @ adj(bf16-hi)
    k_g1<<<dim3(NN / 64, KSM1), 256, smem_g1>>>(spH, adj, gA);
    // tensor GEMM2 (3-term): x0 partials(32) = (sum 8 slabs) @ W0
    k_g2<<<dim3(HN / 64, KSM2), 256>>>(gA, W0, x0p);
    // no-spike validation (approx x0 bound + bias bounds)
    k_validate<<<257, 256>>>(b0, b1, b2);
    // exact persistent simulation (guarded; recomputes exact x0 in prologue)
    k_persist_slow<<<GBLK, 256, smem_slow>>>(spikes, adj, W0, b0,
                                             W1, b1, W2, b2, traces);
    // policy head (fast path writes bp directly)
    k_logits<<<BB, 256>>>(traces, Wp, bp, out);
}

// round 16
// speedup vs baseline: 1.5274x; 1.0068x over previous
#include <cuda_runtime.h>
#include <cuda_bf16.h>
#include <cstdint>

// ---------------- problem constants ----------------
#define HN    256
#define BB    64
#define NN    4096
#define TT    100
#define GBLK  32
#define PAD   72          // bf16 elements per smem row (144 B)

#define V_REST_C   (-70.0f)
#define V_RESET_C  (-75.0f)
#define V_THRESH_C (-55.0f)
#define X_LIMIT_EXACT  2.5f
#define X_LIMIT_TENSOR 2.4f

#define KSM1 8      // mma GEMM1 k-split (Kchunk 512)
#define KSM2 32     // GEMM2 k-split (Kchunk 128)

// ---------------- static device scratch ----------------
__device__ float d_gA[KSM1 * BB * NN];       // GEMM1 mma partials (8 slabs)
__device__ float d_x0[BB * HN];              // b0-init + g2 atomic accumulate
__device__ __nv_bfloat16 d_spH[BB * NN];     // spikes bf16 (hi)
__device__ float d_sp0[BB * HN];
__device__ float d_sp1[BB * HN];
__device__ float d_x1[BB * HN];
__device__ float d_x2[BB * HN];
__device__ unsigned d_barcount;
__device__ unsigned d_bargen;
__device__ unsigned d_need_slow;

// ---------------- helpers ----------------
__device__ __forceinline__ uint32_t cvt_bf2(float x0, float x1) {
    uint32_t r;
    asm("cvt.rn.bf16x2.f32 %0, %1, %2;" : "=r"(r) : "f"(x1), "f"(x0));
    return r;
}
__device__ __forceinline__ uint32_t cvt_bf2_lo(uint32_t h, float x0, float x1) {
    const float d0 = x0 - __uint_as_float(h << 16);
    const float d1 = x1 - __uint_as_float(h & 0xffff0000u);
    return cvt_bf2(d0, d1);
}
__device__ __forceinline__ void cpasync16(uint32_t dst, const void* src) {
    asm volatile("cp.async.cg.shared.global [%0], [%1], 16;" :: "r"(dst), "l"(src));
}
__device__ __forceinline__ void cpasync_commit() {
    asm volatile("cp.async.commit_group;" ::: "memory");
}
template <int N>
__device__ __forceinline__ void cpasync_wait() {
    asm volatile("cp.async.wait_group %0;" :: "n"(N) : "memory");
}
__device__ __forceinline__ void ldmat4(uint32_t* r, uint32_t addr) {
    asm volatile("ldmatrix.sync.aligned.m8n8.x4.shared.b16 {%0,%1,%2,%3}, [%4];"
                 : "=r"(r[0]), "=r"(r[1]), "=r"(r[2]), "=r"(r[3]) : "r"(addr));
}
__device__ __forceinline__ void ldmat4t(uint32_t* r, uint32_t addr) {
    asm volatile("ldmatrix.sync.aligned.m8n8.x4.trans.shared.b16 {%0,%1,%2,%3}, [%4];"
                 : "=r"(r[0]), "=r"(r[1]), "=r"(r[2]), "=r"(r[3]) : "r"(addr));
}
__device__ __forceinline__ void mma16816(float* c, const uint32_t* a,
                                         uint32_t b0, uint32_t b1) {
    asm volatile(
        "mma.sync.aligned.m16n8k16.row.col.f32.bf16.bf16.f32 "
        "{%0,%1,%2,%3}, {%4,%5,%6,%7}, {%8,%9}, {%0,%1,%2,%3};"
        : "+f"(c[0]), "+f"(c[1]), "+f"(c[2]), "+f"(c[3])
        : "r"(a[0]), "r"(a[1]), "r"(a[2]), "r"(a[3]), "r"(b0), "r"(b1));
}

// ---------------- LIF micro-step ----------------
__device__ __forceinline__ void lif_step(float& v, float& isyn, float& refr,
                                         float ib, float& sp) {
    const bool  in_refr = refr > 0.0f;
    const float isyn_u  = isyn + (ib - isyn * 0.2f);
    const float v_u     = v + (isyn_u - (v - V_REST_C)) * 0.05f;
    const bool  spike   = (!in_refr) && (v_u >= V_THRESH_C);
    v    = in_refr ? v    : (spike ? V_RESET_C : v_u);
    isyn = in_refr ? isyn : isyn_u;
    refr = in_refr ? (refr - 1.0f) : (spike ? 2.0f : refr);
    sp   = spike ? 1.0f : 0.0f;
}

// ---------------- grid barrier ----------------
__device__ __forceinline__ void gbar() {
    __syncthreads();
    if (threadIdx.x == 0) {
        __threadfence();
        unsigned gen = *((volatile unsigned*)&d_bargen);
        if (atomicAdd(&d_barcount, 1u) == GBLK - 1u) {
            d_barcount = 0u;
            __threadfence();
            atomicAdd(&d_bargen, 1u);
        } else {
            while (*((volatile unsigned*)&d_bargen) == gen) { }
        }
        __threadfence();
    }
    __syncthreads();
}

// ---------------- prep: zero traces + flag + spikes->bf16 + x0 := b0 -------
__global__ void __launch_bounds__(256) k_prep(float* __restrict__ traces,
                                              const float* __restrict__ spikes,
                                              const float* __restrict__ b0) {
    if (blockIdx.x == 0 && threadIdx.x == 0) d_need_slow = 0u;
    const float4 z = {0.f, 0.f, 0.f, 0.f};
    float4* t4 = (float4*)traces;
    int i = blockIdx.x * 256 + threadIdx.x;
    const int stride = gridDim.x * 256;
    const int n4 = (TT * BB * HN) / 4;
    for (int j = i; j < n4; j += stride) t4[j] = z;
    if (blockIdx.x < 256) {           // convert spikes (65536 float4s)
        const int i4 = blockIdx.x * 256 + threadIdx.x;
        float4 v = __ldg((const float4*)spikes + i4);
        uint2 h;
        h.x = cvt_bf2(v.x, v.y);
        h.y = cvt_bf2(v.z, v.w);
        ((uint2*)d_spH)[i4] = h;
    }
    if (blockIdx.x >= 256 && blockIdx.x < 320) {   // d_x0 := b0 broadcast
        const int i0 = (blockIdx.x - 256) * 256 + threadIdx.x;
        d_x0[i0] = __ldg(b0 + (i0 & 255));
    }
}

// ---------------- GEMM1: g partials = spikes(bf16) @ adj (1-term hh) --------
// BM=64, BN=64, BK=64, Kchunk=512 (T=8), grid (64, 8), 256 thr = 8 warps.
// (verified 47.6us configuration — unchanged)
__global__ void __launch_bounds__(256) k_g1(
    const __nv_bfloat16* __restrict__ AH,
    const float* __restrict__ Bsrc, float* __restrict__ Cp)
{
    extern __shared__ __align__(16) char sm[];
    const uint32_t smBase = (uint32_t)__cvta_generic_to_shared(sm);
    const int AB  = 64 * PAD * 2;        // 9216 B per array
    const int BUF = 2 * AB;              // AH | BH
    const int tid = threadIdx.x;
    const int warp = tid >> 5, lane = tid & 31;
    const int mw = warp & 3, nw = warp >> 2;
    const int n0 = blockIdx.x * 64;
    const int k0 = blockIdx.y * 512;

    float acc[4][4];
#pragma unroll
    for (int j = 0; j < 4; ++j)
#pragma unroll
        for (int c = 0; c < 4; ++c) acc[j][c] = 0.f;

    const int u0 = tid * 2;
    const int br = tid >> 2, bs = (tid & 3) * 16;

    const int lm_m = lane >> 3, lm_r = lane & 7;
    const uint32_t aOff = (uint32_t)(((mw * 16 + (lm_m & 1) * 8 + lm_r) * PAD
                                      + (lm_m >> 1) * 8) * 2);
    const uint32_t bOff = (uint32_t)((((lm_m & 1) * 8 + lm_r) * PAD
                                      + nw * 32 + (lm_m >> 1) * 8) * 2);

    float bf[16];
    {
#pragma unroll
        for (int q = 0; q < 2; ++q) {
            const int u = u0 + q, row = u >> 3, seg = u & 7;
            const uint32_t d = smBase + (uint32_t)((row * PAD + seg * 8) * 2);
            cpasync16(d, AH + (size_t)row * NN + k0 + seg * 8);
        }
        cpasync_commit();
        const float* bp = Bsrc + (size_t)(k0 + br) * NN + n0 + bs;
#pragma unroll
        for (int w = 0; w < 4; ++w) *(float4*)&bf[4 * w] = __ldg((const float4*)bp + w);
    }

    for (int t = 0; t < 8; ++t) {
        const int cur = t & 1;
        {
            uint32_t h[8];
#pragma unroll
            for (int j = 0; j < 8; ++j) h[j] = cvt_bf2(bf[2 * j], bf[2 * j + 1]);
            char* dst = sm + cur * BUF + AB + (br * PAD + bs) * 2;
            *(uint4*)dst        = make_uint4(h[0], h[1], h[2], h[3]);
            *(uint4*)(dst + 16) = make_uint4(h[4], h[5], h[6], h[7]);
        }
        if (t + 1 < 8) {
            const int kt = k0 + (t + 1) * 64;
#pragma unroll
            for (int q = 0; q < 2; ++q) {
                const int u = u0 + q, row = u >> 3, seg = u & 7;
                const uint32_t d = smBase + (uint32_t)((cur ^ 1) * BUF)
                                 + (uint32_t)((row * PAD + seg * 8) * 2);
                cpasync16(d, AH + (size_t)row * NN + kt + seg * 8);
            }
            cpasync_commit();
            const float* bp = Bsrc + (size_t)(kt + br) * NN + n0 + bs;
#pragma unroll
            for (int w = 0; w < 4; ++w)
                *(float4*)&bf[4 * w] = __ldg((const float4*)bp + w);
            cpasync_wait<1>();
        } else {
            cpasync_wait<0>();
        }
        __syncthreads();

        const uint32_t aH_b = smBase + (uint32_t)(cur * BUF) + aOff;
        const uint32_t bH_b = smBase + (uint32_t)(cur * BUF + AB) + bOff;
#pragma unroll
        for (int ks = 0; ks < 4; ++ks) {
            uint32_t a0[4], b0r[4], b1r[4];
            ldmat4(a0, aH_b + ks * 32);
            ldmat4t(b0r, bH_b + (uint32_t)(ks * 16 * PAD * 2));
            ldmat4t(b1r, bH_b + (uint32_t)(ks * 16 * PAD * 2) + 32);
            mma16816(acc[0], a0, b0r[0], b0r[1]);
            mma16816(acc[1], a0, b0r[2], b0r[3]);
            mma16816(acc[2], a0, b1r[0], b1r[1]);
            mma16816(acc[3], a0, b1r[2], b1r[3]);
        }
        __syncthreads();
    }

    float* C = Cp + (size_t)blockIdx.y * (64ull * NN);
    const int g = lane >> 2, tig = lane & 3;
#pragma unroll
    for (int j = 0; j < 4; ++j) {
        const int col = n0 + nw * 32 + j * 8 + tig * 2;
        const int r0 = mw * 16 + g;
        float2 o0 = {acc[j][0], acc[j][1]};
        float2 o1 = {acc[j][2], acc[j][3]};
        *(float2*)&C[(size_t)r0 * NN + col]       = o0;
        *(float2*)&C[(size_t)(r0 + 8) * NN + col] = o1;
    }
}

// ---------------- GEMM2: d_x0 += (sum 8 g slabs) @ W0 (3-term, atomic) ------
// BM=64, BN=64, BK=64, Kchunk=128 (T=2), grid (4, 32). Epilogue atomically
// accumulates into d_x0 (pre-initialized with b0). d_x0 is ONLY used for the
// no-spike certification; the exact fallback recomputes x0 from raw inputs.
__global__ void __launch_bounds__(256) k_g2(
    const float* __restrict__ A, const float* __restrict__ Bsrc)
{
    __shared__ __align__(16) __nv_bfloat16 sAH[64][PAD];
    __shared__ __align__(16) __nv_bfloat16 sAL[64][PAD];
    __shared__ __align__(16) __nv_bfloat16 sBH[64][PAD];
    __shared__ __align__(16) __nv_bfloat16 sBL[64][PAD];
    const int tid = threadIdx.x;
    const int warp = tid >> 5, lane = tid & 31;
    const int mw = warp & 3, nw = warp >> 2;
    const int n0 = blockIdx.x * 64;
    const int k0 = blockIdx.y * 128;

    float acc[4][4];
#pragma unroll
    for (int j = 0; j < 4; ++j)
#pragma unroll
        for (int c = 0; c < 4; ++c) acc[j][c] = 0.f;

    const int ar = tid >> 2, as_ = (tid & 3) * 16;
    const int br = tid >> 2, bs = (tid & 3) * 16;

    const int lm_m = lane >> 3, lm_r = lane & 7;
    const uint32_t aOff = (uint32_t)(((mw * 16 + (lm_m & 1) * 8 + lm_r) * PAD
                                      + (lm_m >> 1) * 8) * 2);
    const uint32_t bOff = (uint32_t)((((lm_m & 1) * 8 + lm_r) * PAD
                                      + nw * 32 + (lm_m >> 1) * 8) * 2);
    const uint32_t aH_b = (uint32_t)__cvta_generic_to_shared(&sAH[0][0]) + aOff;
    const uint32_t aL_b = (uint32_t)__cvta_generic_to_shared(&sAL[0][0]) + aOff;
    const uint32_t bH_b = (uint32_t)__cvta_generic_to_shared(&sBH[0][0]) + bOff;
    const uint32_t bL_b = (uint32_t)__cvta_generic_to_shared(&sBL[0][0]) + bOff;

    float af[16], bf[16];
    {
        const float* ap = A + (size_t)ar * NN + k0 + as_;
#pragma unroll
        for (int w = 0; w < 4; ++w) *(float4*)&af[4 * w] = __ldg((const float4*)ap + w);
#pragma unroll
        for (int p = 1; p < KSM1; ++p) {
            const float* ap2 = ap + (size_t)p * (BB * NN);
#pragma unroll
            for (int w = 0; w < 4; ++w) {
                float4 t = __ldg((const float4*)ap2 + w);
                af[4 * w + 0] += t.x; af[4 * w + 1] += t.y;
                af[4 * w + 2] += t.z; af[4 * w + 3] += t.w;
            }
        }
        const float* bp = Bsrc + (size_t)(k0 + br) * HN + n0 + bs;
#pragma unroll
        for (int w = 0; w < 4; ++w) *(float4*)&bf[4 * w] = __ldg((const float4*)bp + w);
    }

    for (int t = 0; t < 2; ++t) {
        {
            uint32_t h[8], l[8];
#pragma unroll
            for (int j = 0; j < 8; ++j) {
                h[j] = cvt_bf2(af[2 * j], af[2 * j + 1]);
                l[j] = cvt_bf2_lo(h[j], af[2 * j], af[2 * j + 1]);
            }
            *(uint4*)&sAH[ar][as_]     = make_uint4(h[0], h[1], h[2], h[3]);
            *(uint4*)&sAH[ar][as_ + 8] = make_uint4(h[4], h[5], h[6], h[7]);
            *(uint4*)&sAL[ar][as_]     = make_uint4(l[0], l[1], l[2], l[3]);
            *(uint4*)&sAL[ar][as_ + 8] = make_uint4(l[4], l[5], l[6], l[7]);
#pragma unroll
            for (int j = 0; j < 8; ++j) {
                h[j] = cvt_bf2(bf[2 * j], bf[2 * j + 1]);
                l[j] = cvt_bf2_lo(h[j], bf[2 * j], bf[2 * j + 1]);
            }
            *(uint4*)&sBH[br][bs]     = make_uint4(h[0], h[1], h[2], h[3]);
            *(uint4*)&sBH[br][bs + 8] = make_uint4(h[4], h[5], h[6], h[7]);
            *(uint4*)&sBL[br][bs]     = make_uint4(l[0], l[1], l[2], l[3]);
            *(uint4*)&sBL[br][bs + 8] = make_uint4(l[4], l[5], l[6], l[7]);
        }
        if (t + 1 < 2) {
            const int kt = k0 + 64;
            const float* ap = A + (size_t)ar * NN + kt + as_;
#pragma unroll
            for (int w = 0; w < 4; ++w)
                *(float4*)&af[4 * w] = __ldg((const float4*)ap + w);
#pragma unroll
            for (int p = 1; p < KSM1; ++p) {
                const float* ap2 = ap + (size_t)p * (BB * NN);
#pragma unroll
                for (int w = 0; w < 4; ++w) {
                    float4 tt = __ldg((const float4*)ap2 + w);
                    af[4 * w + 0] += tt.x; af[4 * w + 1] += tt.y;
                    af[4 * w + 2] += tt.z; af[4 * w + 3] += tt.w;
                }
            }
            const float* bp = Bsrc + (size_t)(kt + br) * HN + n0 + bs;
#pragma unroll
            for (int w = 0; w < 4; ++w)
                *(float4*)&bf[4 * w] = __ldg((const float4*)bp + w);
        }
        __syncthreads();

#pragma unroll
        for (int ks = 0; ks < 4; ++ks) {
            uint32_t a0[4], a1[4], b0[4], b1[4], c0[4], c1[4];
            ldmat4(a0, aH_b + ks * 32);
            ldmat4(a1, aL_b + ks * 32);
            ldmat4t(b0, bH_b + (uint32_t)(ks * 16 * PAD * 2));
            ldmat4t(b1, bH_b + (uint32_t)(ks * 16 * PAD * 2) + 32);
            ldmat4t(c0, bL_b + (uint32_t)(ks * 16 * PAD * 2));
            ldmat4t(c1, bL_b + (uint32_t)(ks * 16 * PAD * 2) + 32);
            mma16816(acc[0], a0, b0[0], b0[1]);
            mma16816(acc[1], a0, b0[2], b0[3]);
            mma16816(acc[2], a0, b1[0], b1[1]);
            mma16816(acc[3], a0, b1[2], b1[3]);
            mma16816(acc[0], a0, c0[0], c0[1]);
            mma16816(acc[1], a0, c0[2], c0[3]);
            mma16816(acc[2], a0, c1[0], c1[1]);
            mma16816(acc[3], a0, c1[2], c1[3]);
            mma16816(acc[0], a1, b0[0], b0[1]);
            mma16816(acc[1], a1, b0[2], b0[3]);
            mma16816(acc[2], a1, b1[0], b1[1]);
            mma16816(acc[3], a1, b1[2], b1[3]);
        }
        __syncthreads();
    }

    // epilogue: atomic accumulate into d_x0 (certification operand only)
    const int g = lane >> 2, tig = lane & 3;
#pragma unroll
    for (int j = 0; j < 4; ++j) {
        const int col = n0 + nw * 32 + j * 8 + tig * 2;
        const int r0 = mw * 16 + g;
        atomicAdd(&d_x0[(size_t)r0 * HN + col],       acc[j][0]);
        atomicAdd(&d_x0[(size_t)r0 * HN + col + 1],   acc[j][1]);
        atomicAdd(&d_x0[(size_t)(r0 + 8) * HN + col],     acc[j][2]);
        atomicAdd(&d_x0[(size_t)(r0 + 8) * HN + col + 1], acc[j][3]);
    }
}

// ---------------- validate: 64 KB scan of accumulated d_x0 + bias checks ----
__global__ void __launch_bounds__(256) k_validate(const float* __restrict__ b1,
                                                  const float* __restrict__ b2)
{
    const int tid = threadIdx.x;
    int bad;
    if (blockIdx.x < 16) {
        const float4 v = ((const float4*)d_x0)[blockIdx.x * 256 + tid];
        bad = (v.x >= X_LIMIT_TENSOR) | (v.y >= X_LIMIT_TENSOR) |
              (v.z >= X_LIMIT_TENSOR) | (v.w >= X_LIMIT_TENSOR);
    } else {
        bad = (__ldg(b1 + tid) >= X_LIMIT_EXACT) ||
              (__ldg(b2 + tid) >= X_LIMIT_EXACT);
    }
    if (__syncthreads_or(bad) && tid == 0) atomicOr(&d_need_slow, 1u);
}

// ---------------- exact fallback persistent path (guarded) ----------------
__device__ __forceinline__ int stage_to_smem(const float* __restrict__ src,
                                             float* __restrict__ s_x, int tid) {
    const float4* s4 = (const float4*)src;
    float4* dd = (float4*)s_x;
    int flag = 0;
#pragma unroll
    for (int it = 0; it < 16; ++it) {
        const int i = tid + it * 256;
        float4 v = __ldcg(s4 + i);
        flag |= (v.x != 0.f) | (v.y != 0.f) | (v.z != 0.f) | (v.w != 0.f);
        dd[i] = v;
    }
    return flag;
}

__device__ __forceinline__ void gemm_phase(const float* __restrict__ sp,
                                           const float* __restrict__ W,
                                           const float* __restrict__ bias,
                                           float* __restrict__ xout,
                                           int bid, int tid,
                                           float* s_rows, float* s_psum) {
    int flag = 0;
#pragma unroll
    for (int it = 0; it < 2; ++it) {
        const int i = tid + it * 256;
        const float v = __ldcg(sp + bid * 512 + i);
        flag |= (v != 0.f);
        s_rows[i] = v;
    }
    const int tx = tid & 63;
    const int ty = tid >> 6;
    const int c0 = tx * 4;
    const int kb = ty * 64;
    const int any = __syncthreads_or(flag);

    if (any) {
        float4 a0 = {0.f, 0.f, 0.f, 0.f}, a1 = {0.f, 0.f, 0.f, 0.f};
        const float* s0 = s_rows + kb;
        const float* s1 = s_rows + 256 + kb;
#pragma unroll 8
        for (int k = 0; k < 64; ++k) {
            float4 ww = __ldg((const float4*)(W + (size_t)(kb + k) * 256 + c0));
            const float u0 = s0[k], u1 = s1[k];
            a0.x += u0 * ww.x; a0.y += u0 * ww.y; a0.z += u0 * ww.z; a0.w += u0 * ww.w;
            a1.x += u1 * ww.x; a1.y += u1 * ww.y; a1.z += u1 * ww.z; a1.w += u1 * ww.w;
        }
        *(float4*)&s_psum[(ty * 2 + 0) * 256 + c0] = a0;
        *(float4*)&s_psum[(ty * 2 + 1) * 256 + c0] = a1;
        __syncthreads();
        if (ty == 0) {
#pragma unroll
            for (int r = 0; r < 2; ++r) {
                float4 p0 = *(float4*)&s_psum[(0 + r) * 256 + c0];
                float4 p1 = *(float4*)&s_psum[(2 + r) * 256 + c0];
                float4 p2 = *(float4*)&s_psum[(4 + r) * 256 + c0];
                float4 p3 = *(float4*)&s_psum[(6 + r) * 256 + c0];
                float4 bbv = __ldg((const float4*)(bias + c0));
                float4 o;
                o.x = ((p0.x + p1.x) + (p2.x + p3.x)) + bbv.x;
                o.y = ((p0.y + p1.y) + (p2.y + p3.y)) + bbv.y;
                o.z = ((p0.z + p1.z) + (p2.z + p3.z)) + bbv.z;
                o.w = ((p0.w + p1.w) + (p2.w + p3.w)) + bbv.w;
                *(float4*)(xout + (size_t)(bid * 2 + r) * 256 + c0) = o;
            }
        }
        __syncthreads();
    } else {
        if (ty == 0) {
            float4 bbv = __ldg((const float4*)(bias + c0));
#pragma unroll
            for (int r = 0; r < 2; ++r)
                *(float4*)(xout + (size_t)(bid * 2 + r) * 256 + c0) = bbv;
        }
        __syncthreads();
    }
}

__device__ __forceinline__ void lif_scan_layer(const float* __restrict__ xin,
                                               float* __restrict__ spout,
                                               float& v, float& isyn, float& refr,
                                               int tid, float* s_x) {
    int flag = stage_to_smem(xin, s_x, tid);
    flag |= (v != V_REST_C) | (isyn != 0.f) | (refr != 0.f);
    const int any = __syncthreads_or(flag);
    if (any) {
        float nxt = s_x[tid];
#pragma unroll 4
        for (int b = 0; b < 64; ++b) {
            const float ib = nxt;
            if (b < 63) nxt = s_x[(b + 1) * 256 + tid];
            float sp;
            lif_step(v, isyn, refr, ib, sp);
            spout[b * 256 + tid] = sp;
        }
    } else {
        const float4 z = {0.f, 0.f, 0.f, 0.f};
        float4* o4 = (float4*)spout;
#pragma unroll
        for (int it = 0; it < 16; ++it) o4[tid + it * 256] = z;
    }
    __syncthreads();
}

// Exact persistent simulation. Guarded prologue recomputes x0 in exact fp32
// from the raw inputs (naive smem-staged GEMM; never taken on the fast path).
__global__ void __launch_bounds__(256) k_persist_slow(
    const float* __restrict__ spikes, const float* __restrict__ adj,
    const float* __restrict__ W0, const float* __restrict__ b0,
    const float* __restrict__ W1, const float* __restrict__ b1,
    const float* __restrict__ W2, const float* __restrict__ b2,
    float* __restrict__ traces)
{
    if (atomicOr(&d_need_slow, 0u) == 0u) return;

    extern __shared__ float sh[];
    float* s_x    = sh;
    float* s_rows = sh + 16384;
    float* s_psum = sh + 16896;
    const int tid = threadIdx.x;
    const int bid = blockIdx.x;

    // ---- exact x0 for rows bid*2 .. bid*2+1 (slow, correct, never taken) ----
    {
        const int r0 = bid * 2;
        for (int j = tid; j < 2 * NN; j += 256)
            s_x[j] = __ldg(spikes + (size_t)(r0 + (j >> 12)) * NN + (j & (NN - 1)));
        __syncthreads();
        for (int r = 0; r < 2; ++r) {
            const float* arow = s_x + r * NN;
            for (int i = 0; i < NN / 256; ++i) {
                const int n = tid + i * 256;
                float accv = 0.f;
                for (int k = 0; k < NN; ++k)
                    accv = fmaf(arow[k], __ldg(adj + (size_t)k * NN + n), accv);
                s_x[2 * NN + r * NN + n] = accv;
            }
        }
        __syncthreads();
        for (int r = 0; r < 2; ++r) {
            const float* grow = s_x + 2 * NN + r * NN;
            float accv = 0.f;
            for (int n = 0; n < NN; ++n)
                accv = fmaf(grow[n], __ldg(W0 + (size_t)n * HN + tid), accv);
            d_x0[(r0 + r) * HN + tid] = accv + __ldg(b0 + tid);
        }
    }
    gbar();

    float v0 = V_REST_C, i0 = 0.f, r0s = 0.f;
    float v1 = V_REST_C, i1 = 0.f, r1s = 0.f;
    float v2 = V_REST_C, i2 = 0.f, r2s = 0.f;
    const float* x0pre = d_x0;

    for (int t = 0; t < TT; ++t) {
        if (bid == 0) {
            float nxt = __ldg(x0pre + tid);
#pragma unroll 4
            for (int b = 0; b < 64; ++b) {
                const float ib = nxt;
                if (b < 63) nxt = __ldg(x0pre + (b + 1) * 256 + tid);
                float sp;
                lif_step(v0, i0, r0s, ib, sp);
                d_sp0[b * 256 + tid] = sp;
            }
        }
        gbar();
        gemm_phase(d_sp0, W1, b1, d_x1, bid, tid, s_rows, s_psum);
        gbar();
        if (bid == 0) lif_scan_layer(d_x1, d_sp1, v1, i1, r1s, tid, s_x);
        gbar();
        gemm_phase(d_sp1, W2, b2, d_x2, bid, tid, s_rows, s_psum);
        gbar();
        if (bid == 0) lif_scan_layer(d_x2, traces + (size_t)t * (BB * HN),
                                     v2, i2, r2s, tid, s_x);
    }
}

// ---------------- logits (guarded fast path) ----------------
__global__ void __launch_bounds__(256) k_logits(const float* __restrict__ traces,
                                                const float* __restrict__ Wp,
                                                const float* __restrict__ bp,
                                                float* __restrict__ out)
{
    __shared__ float hrow[HN];
    const int b = blockIdx.x;
    const int tid = threadIdx.x;
    if (*((volatile unsigned*)&d_need_slow) == 0u) {
        if (tid < 5) out[b * 5 + tid] = __ldg(bp + tid);
        return;
    }
    float s = 0.f;
    for (int t = 0; t < TT; ++t)
        s += traces[(size_t)t * (BB * HN) + b * HN + tid];
    hrow[tid] = __fdiv_rn(s, 100.0f);
    __syncthreads();
    if (tid < 5) {
        float acc = 0.f;
        for (int h = 0; h < HN; ++h)
            acc += hrow[h] * __ldg(Wp + h * 5 + tid);
        out[b * 5 + tid] = acc + __ldg(bp + tid);
    }
}

// ---------------- launch ----------------
extern "C" void kernel_launch(void* const* d_in, const int* in_sizes, int n_in,
                              void* d_out, int out_size) {
    const float* spikes = (const float*)d_in[0];
    const float* adj    = (const float*)d_in[1];
    const float* W0     = (const float*)d_in[2];
    const float* b0     = (const float*)d_in[3];
    const float* W1     = (const float*)d_in[4];
    const float* b1     = (const float*)d_in[5];
    const float* W2     = (const float*)d_in[6];
    const float* b2     = (const float*)d_in[7];
    const float* Wp     = (const float*)d_in[8];
    const float* bp     = (const float*)d_in[9];
    float* out = (float*)d_out;        // [logits(64*5) | traces(100*64*256)]
    float* traces = out + BB * 5;

    const int smem_slow = (16384 + 512 + 2048) * (int)sizeof(float);
    const int smem_g1   = 2 * 2 * 64 * PAD * 2;      // 36864 B (AH|BH x2 bufs)
    cudaFuncSetAttribute(k_persist_slow, cudaFuncAttributeMaxDynamicSharedMemorySize,
                         smem_slow);
    cudaFuncSetAttribute(k_g1, cudaFuncAttributeMaxDynamicSharedMemorySize,
                         smem_g1);

    void* p;
    cudaGetSymbolAddress(&p, d_gA);   float* gA  = (float*)p;
    cudaGetSymbolAddress(&p, d_spH);  __nv_bfloat16* spH = (__nv_bfloat16*)p;

    // prep: zero traces + reset flag + spikes -> bf16 + d_x0 := b0
    k_prep<<<400, 256>>>(traces, spikes, b0);
    // tensor GEMM1 (1-term hh): g partials(8) = spikes(bf16) @ adj(bf16-hi)
    k_g1<<<dim3(NN / 64, KSM1), 256, smem_g1>>>(spH, adj, gA);
    // tensor GEMM2 (3-term): d_x0 += (sum 8 slabs) @ W0 (atomic epilogue)
    k_g2<<<dim3(HN / 64, KSM2), 256>>>(gA, W0);
    // no-spike validation (tiny: 64 KB d_x0 scan + bias bounds)
    k_validate<<<17, 256>>>(b1, b2);
    // exact persistent simulation (guarded; recomputes exact x0 in prologue)
    k_persist_slow<<<GBLK, 256, smem_slow>>>(spikes, adj, W0, b0,
                                             W1, b1, W2, b2, traces);
    // policy head (fast path writes bp directly)
    k_logits<<<BB, 256>>>(traces, Wp, bp, out);
}

// round 17
// speedup vs baseline: 1.7301x; 1.1327x over previous
#include <cuda_runtime.h>
#include <cuda_bf16.h>
#include <cstdint>

// ---------------- problem constants ----------------
#define HN    256
#define BB    64
#define NN    4096
#define TT    100
#define GBLK  32
#define PAD   72          // bf16 elements per smem row (144 B)

#define V_REST_C   (-70.0f)
#define V_RESET_C  (-75.0f)
#define V_THRESH_C (-55.0f)
#define X_LIMIT_EXACT  2.5f
#define X_LIMIT_TENSOR 2.4f

#define KSM1 8      // mma GEMM1 k-split (Kchunk 512)
#define KSM2 32     // GEMM2 k-split (Kchunk 128)

// ---------------- static device scratch ----------------
__device__ float d_gA[KSM1 * BB * NN];       // GEMM1 mma partials (8 slabs)
__device__ float d_x0[BB * HN];              // b0-init + g2 atomic accumulate
__device__ __nv_bfloat16 d_spH[BB * NN];     // spikes bf16 (hi)
__device__ float d_sp0[BB * HN];
__device__ float d_sp1[BB * HN];
__device__ float d_x1[BB * HN];
__device__ float d_x2[BB * HN];
__device__ unsigned d_barcount;
__device__ unsigned d_bargen;

// ---------------- helpers ----------------
__device__ __forceinline__ uint32_t cvt_bf2(float x0, float x1) {
    uint32_t r;
    asm("cvt.rn.bf16x2.f32 %0, %1, %2;" : "=r"(r) : "f"(x1), "f"(x0));
    return r;
}
__device__ __forceinline__ uint32_t cvt_bf2_lo(uint32_t h, float x0, float x1) {
    const float d0 = x0 - __uint_as_float(h << 16);
    const float d1 = x1 - __uint_as_float(h & 0xffff0000u);
    return cvt_bf2(d0, d1);
}
__device__ __forceinline__ void cpasync16(uint32_t dst, const void* src) {
    asm volatile("cp.async.cg.shared.global [%0], [%1], 16;" :: "r"(dst), "l"(src));
}
__device__ __forceinline__ void cpasync_commit() {
    asm volatile("cp.async.commit_group;" ::: "memory");
}
template <int N>
__device__ __forceinline__ void cpasync_wait() {
    asm volatile("cp.async.wait_group %0;" :: "n"(N) : "memory");
}
__device__ __forceinline__ void ldmat4(uint32_t* r, uint32_t addr) {
    asm volatile("ldmatrix.sync.aligned.m8n8.x4.shared.b16 {%0,%1,%2,%3}, [%4];"
                 : "=r"(r[0]), "=r"(r[1]), "=r"(r[2]), "=r"(r[3]) : "r"(addr));
}
__device__ __forceinline__ void ldmat4t(uint32_t* r, uint32_t addr) {
    asm volatile("ldmatrix.sync.aligned.m8n8.x4.trans.shared.b16 {%0,%1,%2,%3}, [%4];"
                 : "=r"(r[0]), "=r"(r[1]), "=r"(r[2]), "=r"(r[3]) : "r"(addr));
}
__device__ __forceinline__ void mma16816(float* c, const uint32_t* a,
                                         uint32_t b0, uint32_t b1) {
    asm volatile(
        "mma.sync.aligned.m16n8k16.row.col.f32.bf16.bf16.f32 "
        "{%0,%1,%2,%3}, {%4,%5,%6,%7}, {%8,%9}, {%0,%1,%2,%3};"
        : "+f"(c[0]), "+f"(c[1]), "+f"(c[2]), "+f"(c[3])
        : "r"(a[0]), "r"(a[1]), "r"(a[2]), "r"(a[3]), "r"(b0), "r"(b1));
}

// ---------------- LIF micro-step ----------------
__device__ __forceinline__ void lif_step(float& v, float& isyn, float& refr,
                                         float ib, float& sp) {
    const bool  in_refr = refr > 0.0f;
    const float isyn_u  = isyn + (ib - isyn * 0.2f);
    const float v_u     = v + (isyn_u - (v - V_REST_C)) * 0.05f;
    const bool  spike   = (!in_refr) && (v_u >= V_THRESH_C);
    v    = in_refr ? v    : (spike ? V_RESET_C : v_u);
    isyn = in_refr ? isyn : isyn_u;
    refr = in_refr ? (refr - 1.0f) : (spike ? 2.0f : refr);
    sp   = spike ? 1.0f : 0.0f;
}

// ---------------- grid barrier ----------------
__device__ __forceinline__ void gbar() {
    __syncthreads();
    if (threadIdx.x == 0) {
        __threadfence();
        unsigned gen = *((volatile unsigned*)&d_bargen);
        if (atomicAdd(&d_barcount, 1u) == GBLK - 1u) {
            d_barcount = 0u;
            __threadfence();
            atomicAdd(&d_bargen, 1u);
        } else {
            while (*((volatile unsigned*)&d_bargen) == gen) { }
        }
        __threadfence();
    }
    __syncthreads();
}

// ---------------- per-block no-spike verdict (deterministic OR-scan) -------
// Reads post-g2 d_x0 (64 KB, L2-resident) + bias vectors. Every block in
// every kernel computes the identical verdict (OR is order-invariant).
__device__ __forceinline__ int need_slow_scan(const float* __restrict__ b1,
                                              const float* __restrict__ b2,
                                              int tid) {
    int bad = 0;
    const float4* x4 = (const float4*)d_x0;
#pragma unroll
    for (int i = 0; i < 16; ++i) {
        const float4 v = __ldcg(x4 + tid + i * 256);
        bad |= (v.x >= X_LIMIT_TENSOR) | (v.y >= X_LIMIT_TENSOR) |
               (v.z >= X_LIMIT_TENSOR) | (v.w >= X_LIMIT_TENSOR);
    }
    bad |= (__ldg(b1 + tid) >= X_LIMIT_EXACT) |
           (__ldg(b2 + tid) >= X_LIMIT_EXACT);
    return __syncthreads_or(bad);
}

// ---------------- prep: spikes->bf16 + x0 := b0 ----------------------------
__global__ void __launch_bounds__(256) k_prep(const float* __restrict__ spikes,
                                              const float* __restrict__ b0) {
    if (blockIdx.x < 256) {           // convert spikes (65536 float4s)
        const int i4 = blockIdx.x * 256 + threadIdx.x;
        float4 v = __ldg((const float4*)spikes + i4);
        uint2 h;
        h.x = cvt_bf2(v.x, v.y);
        h.y = cvt_bf2(v.z, v.w);
        ((uint2*)d_spH)[i4] = h;
    } else {                          // d_x0 := b0 broadcast (64 blocks)
        const int i0 = (blockIdx.x - 256) * 256 + threadIdx.x;
        d_x0[i0] = __ldg(b0 + (i0 & 255));
    }
}

// ---------------- GEMM1: g partials = spikes(bf16) @ adj (1-term hh) --------
// BM=64, BN=64, BK=64, Kchunk=512 (T=8), grid (64, 8), 256 thr = 8 warps.
// Also zeroes its 12.8 KB slice of traces (overlapped with prologue loads).
__global__ void __launch_bounds__(256) k_g1(
    const __nv_bfloat16* __restrict__ AH,
    const float* __restrict__ Bsrc, float* __restrict__ Cp,
    float* __restrict__ traces)
{
    extern __shared__ __align__(16) char sm[];
    const uint32_t smBase = (uint32_t)__cvta_generic_to_shared(sm);
    const int AB  = 64 * PAD * 2;        // 9216 B per array
    const int BUF = 2 * AB;              // AH | BH
    const int tid = threadIdx.x;
    const int warp = tid >> 5, lane = tid & 31;
    const int mw = warp & 3, nw = warp >> 2;
    const int n0 = blockIdx.x * 64;
    const int k0 = blockIdx.y * 512;

    float acc[4][4];
#pragma unroll
    for (int j = 0; j < 4; ++j)
#pragma unroll
        for (int c = 0; c < 4; ++c) acc[j][c] = 0.f;

    const int u0 = tid * 2;
    const int br = tid >> 2, bs = (tid & 3) * 16;

    const int lm_m = lane >> 3, lm_r = lane & 7;
    const uint32_t aOff = (uint32_t)(((mw * 16 + (lm_m & 1) * 8 + lm_r) * PAD
                                      + (lm_m >> 1) * 8) * 2);
    const uint32_t bOff = (uint32_t)((((lm_m & 1) * 8 + lm_r) * PAD
                                      + nw * 32 + (lm_m >> 1) * 8) * 2);

    float bf[16];
    {
#pragma unroll
        for (int q = 0; q < 2; ++q) {
            const int u = u0 + q, row = u >> 3, seg = u & 7;
            const uint32_t d = smBase + (uint32_t)((row * PAD + seg * 8) * 2);
            cpasync16(d, AH + (size_t)row * NN + k0 + seg * 8);
        }
        cpasync_commit();
        const float* bp = Bsrc + (size_t)(k0 + br) * NN + n0 + bs;
#pragma unroll
        for (int w = 0; w < 4; ++w) *(float4*)&bf[4 * w] = __ldg((const float4*)bp + w);
    }

    // zero this block's slice of traces (512 blocks x 800 float4 = 6.55 MB)
    {
        const int bidl = blockIdx.y * 64 + blockIdx.x;     // 0..511
        float4* t4 = (float4*)traces + (size_t)bidl * 800;
        const float4 z = {0.f, 0.f, 0.f, 0.f};
        for (int j = tid; j < 800; j += 256) t4[j] = z;
    }

    for (int t = 0; t < 8; ++t) {
        const int cur = t & 1;
        {
            uint32_t h[8];
#pragma unroll
            for (int j = 0; j < 8; ++j) h[j] = cvt_bf2(bf[2 * j], bf[2 * j + 1]);
            char* dst = sm + cur * BUF + AB + (br * PAD + bs) * 2;
            *(uint4*)dst        = make_uint4(h[0], h[1], h[2], h[3]);
            *(uint4*)(dst + 16) = make_uint4(h[4], h[5], h[6], h[7]);
        }
        if (t + 1 < 8) {
            const int kt = k0 + (t + 1) * 64;
#pragma unroll
            for (int q = 0; q < 2; ++q) {
                const int u = u0 + q, row = u >> 3, seg = u & 7;
                const uint32_t d = smBase + (uint32_t)((cur ^ 1) * BUF)
                                 + (uint32_t)((row * PAD + seg * 8) * 2);
                cpasync16(d, AH + (size_t)row * NN + kt + seg * 8);
            }
            cpasync_commit();
            const float* bp = Bsrc + (size_t)(kt + br) * NN + n0 + bs;
#pragma unroll
            for (int w = 0; w < 4; ++w)
                *(float4*)&bf[4 * w] = __ldg((const float4*)bp + w);
            cpasync_wait<1>();
        } else {
            cpasync_wait<0>();
        }
        __syncthreads();

        const uint32_t aH_b = smBase + (uint32_t)(cur * BUF) + aOff;
        const uint32_t bH_b = smBase + (uint32_t)(cur * BUF + AB) + bOff;
#pragma unroll
        for (int ks = 0; ks < 4; ++ks) {
            uint32_t a0[4], b0r[4], b1r[4];
            ldmat4(a0, aH_b + ks * 32);
            ldmat4t(b0r, bH_b + (uint32_t)(ks * 16 * PAD * 2));
            ldmat4t(b1r, bH_b + (uint32_t)(ks * 16 * PAD * 2) + 32);
            mma16816(acc[0], a0, b0r[0], b0r[1]);
            mma16816(acc[1], a0, b0r[2], b0r[3]);
            mma16816(acc[2], a0, b1r[0], b1r[1]);
            mma16816(acc[3], a0, b1r[2], b1r[3]);
        }
        __syncthreads();
    }

    float* C = Cp + (size_t)blockIdx.y * (64ull * NN);
    const int g = lane >> 2, tig = lane & 3;
#pragma unroll
    for (int j = 0; j < 4; ++j) {
        const int col = n0 + nw * 32 + j * 8 + tig * 2;
        const int r0 = mw * 16 + g;
        float2 o0 = {acc[j][0], acc[j][1]};
        float2 o1 = {acc[j][2], acc[j][3]};
        *(float2*)&C[(size_t)r0 * NN + col]       = o0;
        *(float2*)&C[(size_t)(r0 + 8) * NN + col] = o1;
    }
}

// ---------------- GEMM2: d_x0 += (sum 8 g slabs) @ W0 (3-term, atomic) ------
// BM=64, BN=64, BK=64, Kchunk=128 (T=2), grid (4, 32).  (verified — unchanged)
__global__ void __launch_bounds__(256) k_g2(
    const float* __restrict__ A, const float* __restrict__ Bsrc)
{
    __shared__ __align__(16) __nv_bfloat16 sAH[64][PAD];
    __shared__ __align__(16) __nv_bfloat16 sAL[64][PAD];
    __shared__ __align__(16) __nv_bfloat16 sBH[64][PAD];
    __shared__ __align__(16) __nv_bfloat16 sBL[64][PAD];
    const int tid = threadIdx.x;
    const int warp = tid >> 5, lane = tid & 31;
    const int mw = warp & 3, nw = warp >> 2;
    const int n0 = blockIdx.x * 64;
    const int k0 = blockIdx.y * 128;

    float acc[4][4];
#pragma unroll
    for (int j = 0; j < 4; ++j)
#pragma unroll
        for (int c = 0; c < 4; ++c) acc[j][c] = 0.f;

    const int ar = tid >> 2, as_ = (tid & 3) * 16;
    const int br = tid >> 2, bs = (tid & 3) * 16;

    const int lm_m = lane >> 3, lm_r = lane & 7;
    const uint32_t aOff = (uint32_t)(((mw * 16 + (lm_m & 1) * 8 + lm_r) * PAD
                                      + (lm_m >> 1) * 8) * 2);
    const uint32_t bOff = (uint32_t)((((lm_m & 1) * 8 + lm_r) * PAD
                                      + nw * 32 + (lm_m >> 1) * 8) * 2);
    const uint32_t aH_b = (uint32_t)__cvta_generic_to_shared(&sAH[0][0]) + aOff;
    const uint32_t aL_b = (uint32_t)__cvta_generic_to_shared(&sAL[0][0]) + aOff;
    const uint32_t bH_b = (uint32_t)__cvta_generic_to_shared(&sBH[0][0]) + bOff;
    const uint32_t bL_b = (uint32_t)__cvta_generic_to_shared(&sBL[0][0]) + bOff;

    float af[16], bf[16];
    {
        const float* ap = A + (size_t)ar * NN + k0 + as_;
#pragma unroll
        for (int w = 0; w < 4; ++w) *(float4*)&af[4 * w] = __ldg((const float4*)ap + w);
#pragma unroll
        for (int p = 1; p < KSM1; ++p) {
            const float* ap2 = ap + (size_t)p * (BB * NN);
#pragma unroll
            for (int w = 0; w < 4; ++w) {
                float4 t = __ldg((const float4*)ap2 + w);
                af[4 * w + 0] += t.x; af[4 * w + 1] += t.y;
                af[4 * w + 2] += t.z; af[4 * w + 3] += t.w;
            }
        }
        const float* bp = Bsrc + (size_t)(k0 + br) * HN + n0 + bs;
#pragma unroll
        for (int w = 0; w < 4; ++w) *(float4*)&bf[4 * w] = __ldg((const float4*)bp + w);
    }

    for (int t = 0; t < 2; ++t) {
        {
            uint32_t h[8], l[8];
#pragma unroll
            for (int j = 0; j < 8; ++j) {
                h[j] = cvt_bf2(af[2 * j], af[2 * j + 1]);
                l[j] = cvt_bf2_lo(h[j], af[2 * j], af[2 * j + 1]);
            }
            *(uint4*)&sAH[ar][as_]     = make_uint4(h[0], h[1], h[2], h[3]);
            *(uint4*)&sAH[ar][as_ + 8] = make_uint4(h[4], h[5], h[6], h[7]);
            *(uint4*)&sAL[ar][as_]     = make_uint4(l[0], l[1], l[2], l[3]);
            *(uint4*)&sAL[ar][as_ + 8] = make_uint4(l[4], l[5], l[6], l[7]);
#pragma unroll
            for (int j = 0; j < 8; ++j) {
                h[j] = cvt_bf2(bf[2 * j], bf[2 * j + 1]);
                l[j] = cvt_bf2_lo(h[j], bf[2 * j], bf[2 * j + 1]);
            }
            *(uint4*)&sBH[br][bs]     = make_uint4(h[0], h[1], h[2], h[3]);
            *(uint4*)&sBH[br][bs + 8] = make_uint4(h[4], h[5], h[6], h[7]);
            *(uint4*)&sBL[br][bs]     = make_uint4(l[0], l[1], l[2], l[3]);
            *(uint4*)&sBL[br][bs + 8] = make_uint4(l[4], l[5], l[6], l[7]);
        }
        if (t + 1 < 2) {
            const int kt = k0 + 64;
            const float* ap = A + (size_t)ar * NN + kt + as_;
#pragma unroll
            for (int w = 0; w < 4; ++w)
                *(float4*)&af[4 * w] = __ldg((const float4*)ap + w);
#pragma unroll
            for (int p = 1; p < KSM1; ++p) {
                const float* ap2 = ap + (size_t)p * (BB * NN);
#pragma unroll
                for (int w = 0; w < 4; ++w) {
                    float4 tt = __ldg((const float4*)ap2 + w);
                    af[4 * w + 0] += tt.x; af[4 * w + 1] += tt.y;
                    af[4 * w + 2] += tt.z; af[4 * w + 3] += tt.w;
                }
            }
            const float* bp = Bsrc + (size_t)(kt + br) * HN + n0 + bs;
#pragma unroll
            for (int w = 0; w < 4; ++w)
                *(float4*)&bf[4 * w] = __ldg((const float4*)bp + w);
        }
        __syncthreads();

#pragma unroll
        for (int ks = 0; ks < 4; ++ks) {
            uint32_t a0[4], a1[4], b0[4], b1[4], c0[4], c1[4];
            ldmat4(a0, aH_b + ks * 32);
            ldmat4(a1, aL_b + ks * 32);
            ldmat4t(b0, bH_b + (uint32_t)(ks * 16 * PAD * 2));
            ldmat4t(b1, bH_b + (uint32_t)(ks * 16 * PAD * 2) + 32);
            ldmat4t(c0, bL_b + (uint32_t)(ks * 16 * PAD * 2));
            ldmat4t(c1, bL_b + (uint32_t)(ks * 16 * PAD * 2) + 32);
            mma16816(acc[0], a0, b0[0], b0[1]);
            mma16816(acc[1], a0, b0[2], b0[3]);
            mma16816(acc[2], a0, b1[0], b1[1]);
            mma16816(acc[3], a0, b1[2], b1[3]);
            mma16816(acc[0], a0, c0[0], c0[1]);
            mma16816(acc[1], a0, c0[2], c0[3]);
            mma16816(acc[2], a0, c1[0], c1[1]);
            mma16816(acc[3], a0, c1[2], c1[3]);
            mma16816(acc[0], a1, b0[0], b0[1]);
            mma16816(acc[1], a1, b0[2], b0[3]);
            mma16816(acc[2], a1, b1[0], b1[1]);
            mma16816(acc[3], a1, b1[2], b1[3]);
        }
        __syncthreads();
    }

    // epilogue: atomic accumulate into d_x0 (certification operand only)
    const int g = lane >> 2, tig = lane & 3;
#pragma unroll
    for (int j = 0; j < 4; ++j) {
        const int col = n0 + nw * 32 + j * 8 + tig * 2;
        const int r0 = mw * 16 + g;
        atomicAdd(&d_x0[(size_t)r0 * HN + col],       acc[j][0]);
        atomicAdd(&d_x0[(size_t)r0 * HN + col + 1],   acc[j][1]);
        atomicAdd(&d_x0[(size_t)(r0 + 8) * HN + col],     acc[j][2]);
        atomicAdd(&d_x0[(size_t)(r0 + 8) * HN + col + 1], acc[j][3]);
    }
}

// ---------------- exact fallback persistent path (guarded) ----------------
__device__ __forceinline__ int stage_to_smem(const float* __restrict__ src,
                                             float* __restrict__ s_x, int tid) {
    const float4* s4 = (const float4*)src;
    float4* dd = (float4*)s_x;
    int flag = 0;
#pragma unroll
    for (int it = 0; it < 16; ++it) {
        const int i = tid + it * 256;
        float4 v = __ldcg(s4 + i);
        flag |= (v.x != 0.f) | (v.y != 0.f) | (v.z != 0.f) | (v.w != 0.f);
        dd[i] = v;
    }
    return flag;
}

__device__ __forceinline__ void gemm_phase(const float* __restrict__ sp,
                                           const float* __restrict__ W,
                                           const float* __restrict__ bias,
                                           float* __restrict__ xout,
                                           int bid, int tid,
                                           float* s_rows, float* s_psum) {
    int flag = 0;
#pragma unroll
    for (int it = 0; it < 2; ++it) {
        const int i = tid + it * 256;
        const float v = __ldcg(sp + bid * 512 + i);
        flag |= (v != 0.f);
        s_rows[i] = v;
    }
    const int tx = tid & 63;
    const int ty = tid >> 6;
    const int c0 = tx * 4;
    const int kb = ty * 64;
    const int any = __syncthreads_or(flag);

    if (any) {
        float4 a0 = {0.f, 0.f, 0.f, 0.f}, a1 = {0.f, 0.f, 0.f, 0.f};
        const float* s0 = s_rows + kb;
        const float* s1 = s_rows + 256 + kb;
#pragma unroll 8
        for (int k = 0; k < 64; ++k) {
            float4 ww = __ldg((const float4*)(W + (size_t)(kb + k) * 256 + c0));
            const float u0 = s0[k], u1 = s1[k];
            a0.x += u0 * ww.x; a0.y += u0 * ww.y; a0.z += u0 * ww.z; a0.w += u0 * ww.w;
            a1.x += u1 * ww.x; a1.y += u1 * ww.y; a1.z += u1 * ww.z; a1.w += u1 * ww.w;
        }
        *(float4*)&s_psum[(ty * 2 + 0) * 256 + c0] = a0;
        *(float4*)&s_psum[(ty * 2 + 1) * 256 + c0] = a1;
        __syncthreads();
        if (ty == 0) {
#pragma unroll
            for (int r = 0; r < 2; ++r) {
                float4 p0 = *(float4*)&s_psum[(0 + r) * 256 + c0];
                float4 p1 = *(float4*)&s_psum[(2 + r) * 256 + c0];
                float4 p2 = *(float4*)&s_psum[(4 + r) * 256 + c0];
                float4 p3 = *(float4*)&s_psum[(6 + r) * 256 + c0];
                float4 bbv = __ldg((const float4*)(bias + c0));
                float4 o;
                o.x = ((p0.x + p1.x) + (p2.x + p3.x)) + bbv.x;
                o.y = ((p0.y + p1.y) + (p2.y + p3.y)) + bbv.y;
                o.z = ((p0.z + p1.z) + (p2.z + p3.z)) + bbv.z;
                o.w = ((p0.w + p1.w) + (p2.w + p3.w)) + bbv.w;
                *(float4*)(xout + (size_t)(bid * 2 + r) * 256 + c0) = o;
            }
        }
        __syncthreads();
    } else {
        if (ty == 0) {
            float4 bbv = __ldg((const float4*)(bias + c0));
#pragma unroll
            for (int r = 0; r < 2; ++r)
                *(float4*)(xout + (size_t)(bid * 2 + r) * 256 + c0) = bbv;
        }
        __syncthreads();
    }
}

__device__ __forceinline__ void lif_scan_layer(const float* __restrict__ xin,
                                               float* __restrict__ spout,
                                               float& v, float& isyn, float& refr,
                                               int tid, float* s_x) {
    int flag = stage_to_smem(xin, s_x, tid);
    flag |= (v != V_REST_C) | (isyn != 0.f) | (refr != 0.f);
    const int any = __syncthreads_or(flag);
    if (any) {
        float nxt = s_x[tid];
#pragma unroll 4
        for (int b = 0; b < 64; ++b) {
            const float ib = nxt;
            if (b < 63) nxt = s_x[(b + 1) * 256 + tid];
            float sp;
            lif_step(v, isyn, refr, ib, sp);
            spout[b * 256 + tid] = sp;
        }
    } else {
        const float4 z = {0.f, 0.f, 0.f, 0.f};
        float4* o4 = (float4*)spout;
#pragma unroll
        for (int it = 0; it < 16; ++it) o4[tid + it * 256] = z;
    }
    __syncthreads();
}

// Exact persistent simulation. Per-block verdict scan replaces the flag; the
// guarded prologue recomputes x0 in exact fp32 from raw inputs.
__global__ void __launch_bounds__(256) k_persist_slow(
    const float* __restrict__ spikes, const float* __restrict__ adj,
    const float* __restrict__ W0, const float* __restrict__ b0,
    const float* __restrict__ W1, const float* __restrict__ b1,
    const float* __restrict__ W2, const float* __restrict__ b2,
    float* __restrict__ traces)
{
    extern __shared__ float sh[];
    float* s_x    = sh;
    float* s_rows = sh + 16384;
    float* s_psum = sh + 16896;
    const int tid = threadIdx.x;
    const int bid = blockIdx.x;

    if (!need_slow_scan(b1, b2, tid)) return;    // certified spike-free

    // ---- exact x0 for rows bid*2 .. bid*2+1 (slow, correct, never taken) ----
    {
        const int r0 = bid * 2;
        for (int j = tid; j < 2 * NN; j += 256)
            s_x[j] = __ldg(spikes + (size_t)(r0 + (j >> 12)) * NN + (j & (NN - 1)));
        __syncthreads();
        for (int r = 0; r < 2; ++r) {
            const float* arow = s_x + r * NN;
            for (int i = 0; i < NN / 256; ++i) {
                const int n = tid + i * 256;
                float accv = 0.f;
                for (int k = 0; k < NN; ++k)
                    accv = fmaf(arow[k], __ldg(adj + (size_t)k * NN + n), accv);
                s_x[2 * NN + r * NN + n] = accv;
            }
        }
        __syncthreads();
        for (int r = 0; r < 2; ++r) {
            const float* grow = s_x + 2 * NN + r * NN;
            float accv = 0.f;
            for (int n = 0; n < NN; ++n)
                accv = fmaf(grow[n], __ldg(W0 + (size_t)n * HN + tid), accv);
            d_x0[(r0 + r) * HN + tid] = accv + __ldg(b0 + tid);
        }
    }
    gbar();

    float v0 = V_REST_C, i0 = 0.f, r0s = 0.f;
    float v1 = V_REST_C, i1 = 0.f, r1s = 0.f;
    float v2 = V_REST_C, i2 = 0.f, r2s = 0.f;
    const float* x0pre = d_x0;

    for (int t = 0; t < TT; ++t) {
        if (bid == 0) {
            float nxt = __ldg(x0pre + tid);
#pragma unroll 4
            for (int b = 0; b < 64; ++b) {
                const float ib = nxt;
                if (b < 63) nxt = __ldg(x0pre + (b + 1) * 256 + tid);
                float sp;
                lif_step(v0, i0, r0s, ib, sp);
                d_sp0[b * 256 + tid] = sp;
            }
        }
        gbar();
        gemm_phase(d_sp0, W1, b1, d_x1, bid, tid, s_rows, s_psum);
        gbar();
        if (bid == 0) lif_scan_layer(d_x1, d_sp1, v1, i1, r1s, tid, s_x);
        gbar();
        gemm_phase(d_sp1, W2, b2, d_x2, bid, tid, s_rows, s_psum);
        gbar();
        if (bid == 0) lif_scan_layer(d_x2, traces + (size_t)t * (BB * HN),
                                     v2, i2, r2s, tid, s_x);
    }
}

// ---------------- logits (per-block verdict; fast path = bp) ----------------
__global__ void __launch_bounds__(256) k_logits(const float* __restrict__ traces,
                                                const float* __restrict__ Wp,
                                                const float* __restrict__ bp,
                                                const float* __restrict__ b1,
                                                const float* __restrict__ b2,
                                                float* __restrict__ out)
{
    __shared__ float hrow[HN];
    const int b = blockIdx.x;
    const int tid = threadIdx.x;
    if (!need_slow_scan(b1, b2, tid)) {
        if (tid < 5) out[b * 5 + tid] = __ldg(bp + tid);
        return;
    }
    float s = 0.f;
    for (int t = 0; t < TT; ++t)
        s += traces[(size_t)t * (BB * HN) + b * HN + tid];
    hrow[tid] = __fdiv_rn(s, 100.0f);
    __syncthreads();
    if (tid < 5) {
        float acc = 0.f;
        for (int h = 0; h < HN; ++h)
            acc += hrow[h] * __ldg(Wp + h * 5 + tid);
        out[b * 5 + tid] = acc + __ldg(bp + tid);
    }
}

// ---------------- launch ----------------
extern "C" void kernel_launch(void* const* d_in, const int* in_sizes, int n_in,
                              void* d_out, int out_size) {
    const float* spikes = (const float*)d_in[0];
    const float* adj    = (const float*)d_in[1];
    const float* W0     = (const float*)d_in[2];
    const float* b0     = (const float*)d_in[3];
    const float* W1     = (const float*)d_in[4];
    const float* b1     = (const float*)d_in[5];
    const float* W2     = (const float*)d_in[6];
    const float* b2     = (const float*)d_in[7];
    const float* Wp     = (const float*)d_in[8];
    const float* bp     = (const float*)d_in[9];
    float* out = (float*)d_out;        // [logits(64*5) | traces(100*64*256)]
    float* traces = out + BB * 5;

    const int smem_slow = (16384 + 512 + 2048) * (int)sizeof(float);
    const int smem_g1   = 2 * 2 * 64 * PAD * 2;      // 36864 B (AH|BH x2 bufs)
    cudaFuncSetAttribute(k_persist_slow, cudaFuncAttributeMaxDynamicSharedMemorySize,
                         smem_slow);
    cudaFuncSetAttribute(k_g1, cudaFuncAttributeMaxDynamicSharedMemorySize,
                         smem_g1);

    void* p;
    cudaGetSymbolAddress(&p, d_gA);   float* gA  = (float*)p;
    cudaGetSymbolAddress(&p, d_spH);  __nv_bfloat16* spH = (__nv_bfloat16*)p;

    // prep: spikes -> bf16, d_x0 := b0
    k_prep<<<320, 256>>>(spikes, b0);
    // tensor GEMM1 (1-term hh) + zero traces slice per block
    k_g1<<<dim3(NN / 64, KSM1), 256, smem_g1>>>(spH, adj, gA, traces);
    // tensor GEMM2 (3-term): d_x0 += (sum 8 slabs) @ W0 (atomic epilogue)
    k_g2<<<dim3(HN / 64, KSM2), 256>>>(gA, W0);
    // exact persistent simulation (per-block verdict; early-exits when
    // certified spike-free; recomputes exact x0 in prologue otherwise)
    k_persist_slow<<<GBLK, 256, smem_slow>>>(spikes, adj, W0, b0,
                                             W1, b1, W2, b2, traces);
    // policy head (per-block verdict; fast path writes bp directly)
    k_logits<<<BB, 256>>>(traces, Wp, bp, b1, b2, out);
}